// round 5
// baseline (speedup 1.0000x reference)
#include <cuda_runtime.h>
#include <cuda_bf16.h>
#include <math.h>
#include <float.h>

// Problem constants
#define B_  4
#define S_  1024
#define E_  2048
#define H_  16
#define DH_ 128
#define F_  8192
#define M_  (B_ * S_)          // 4096 rows

// ---------------------------------------------------------------------------
// Scratch (device globals; allocation-free contract)
// ---------------------------------------------------------------------------
__device__ float g_y   [(size_t)M_ * E_];        //  32 MB  LN1 out
__device__ float g_yp  [(size_t)M_ * E_];        //  32 MB  rope(LN1)
__device__ float g_q   [(size_t)M_ * E_];        //  32 MB  [B,S,H,DH]
__device__ float g_k   [(size_t)M_ * E_];        //  32 MB
__device__ float g_v   [(size_t)M_ * E_];        //  32 MB
__device__ float g_sc  [(size_t)B_ * H_ * S_ * S_]; // 256 MB scores/probs
__device__ float g_ctx [(size_t)M_ * E_];        //  32 MB
__device__ float g_attn[(size_t)M_ * E_];        //  32 MB
__device__ float g_z   [(size_t)M_ * E_];        //  32 MB
__device__ float g_G   [(size_t)M_ * F_];        // 128 MB gate
__device__ float g_U   [(size_t)M_ * F_];        // 128 MB up

// ---------------------------------------------------------------------------
// LayerNorm (+ optional RoPE) — one block per row
// ---------------------------------------------------------------------------
template<bool ROPE>
__global__ void __launch_bounds__(256)
ln_kernel(const float* __restrict__ x,
          const float* __restrict__ gamma, const float* __restrict__ beta,
          float* __restrict__ y, float* __restrict__ yp)
{
    __shared__ float sy[E_];
    __shared__ float red[256];
    const int r   = blockIdx.x;          // b*S + s
    const int s   = r & (S_ - 1);
    const int tid = threadIdx.x;
    const float* xr = x + (long long)r * E_;

    float sum = 0.f;
    #pragma unroll
    for (int i = tid; i < E_; i += 256) { float v = xr[i]; sy[i] = v; sum += v; }
    red[tid] = sum; __syncthreads();
    #pragma unroll
    for (int o = 128; o > 0; o >>= 1) { if (tid < o) red[tid] += red[tid + o]; __syncthreads(); }
    const float mean = red[0] * (1.0f / E_);
    __syncthreads();

    float vs = 0.f;
    #pragma unroll
    for (int i = tid; i < E_; i += 256) { float d = sy[i] - mean; vs += d * d; }
    red[tid] = vs; __syncthreads();
    #pragma unroll
    for (int o = 128; o > 0; o >>= 1) { if (tid < o) red[tid] += red[tid + o]; __syncthreads(); }
    const float rstd = rsqrtf(red[0] * (1.0f / E_) + 1e-6f);
    __syncthreads();

    #pragma unroll
    for (int i = tid; i < E_; i += 256) {
        float v = (sy[i] - mean) * rstd * gamma[i] + beta[i];
        y[(long long)r * E_ + i] = v;
        sy[i] = v;
    }
    if (ROPE) {
        __syncthreads();
        const float l2c = 13.287712379549449f / 1024.0f;  // log2(10000)/half
        #pragma unroll
        for (int i = tid; i < E_; i += 256) {
            int j = (i < 1024) ? i : (i - 1024);
            float ang = (float)s * exp2f(-(float)j * l2c);
            float c, sn;
            sincosf(ang, &sn, &c);
            float rot = (i < 1024) ? -sy[i + 1024] : sy[i - 1024];
            yp[(long long)r * E_ + i] = sy[i] * c + rot * sn;
        }
    }
}

// ---------------------------------------------------------------------------
// Generic 128x128x8 SGEMM, 256 threads, 8x8 per thread (4+4 split tiling).
// Batched via z: b = z / Hdiv, h = z % Hdiv; per-operand (b,h) strides.
// TRANSB: B is [N,K] row-major (C = A * B^T). CAUSAL: skip tiles with bx > by.
// All of M, N multiple of 128; K multiple of 8; ld* multiple of 4.
// ---------------------------------------------------------------------------
template<bool TRANSB, bool CAUSAL>
__global__ void __launch_bounds__(256)
sgemm_kernel(const float* __restrict__ A, const float* __restrict__ Bm,
             float* __restrict__ C,
             int K, int lda, int ldb, int ldc,
             long long sAb, long long sAh,
             long long sBb, long long sBh,
             long long sCb, long long sCh,
             int Hdiv, float alpha)
{
    if (CAUSAL && blockIdx.x > blockIdx.y) return;

    const int z  = blockIdx.z;
    const int bb = z / Hdiv;
    const int hh = z - bb * Hdiv;
    A  += bb * sAb + hh * sAh;
    Bm += bb * sBb + hh * sBh;
    C  += bb * sCb + hh * sCh;

    __shared__ __align__(16) float As[8][128];
    __shared__ __align__(16) float Bs[8][128];

    const int tid = threadIdx.x;
    const int tx  = tid & 15;
    const int ty  = tid >> 4;

    const int rowBase = blockIdx.y * 128;
    const int colBase = blockIdx.x * 128;

    const int arow = tid >> 1;          // 0..127
    const int acol = (tid & 1) * 4;     // 0 or 4
    const int brow = tid >> 5;          // 0..7   (NN)
    const int bcol = (tid & 31) * 4;    // 0..124 (NN)

    float acc[8][8];
    #pragma unroll
    for (int i = 0; i < 8; i++)
        #pragma unroll
        for (int j = 0; j < 8; j++) acc[i][j] = 0.f;

    const float* Aptr = A + (long long)(rowBase + arow) * lda + acol;
    const float* Bptr = TRANSB
        ? Bm + (long long)(colBase + arow) * ldb + acol
        : Bm + (long long)brow * ldb + colBase + bcol;

    for (int k0 = 0; k0 < K; k0 += 8) {
        float4 av = *(const float4*)(Aptr + k0);
        As[acol + 0][arow] = av.x;
        As[acol + 1][arow] = av.y;
        As[acol + 2][arow] = av.z;
        As[acol + 3][arow] = av.w;
        if (TRANSB) {
            float4 bv = *(const float4*)(Bptr + k0);
            Bs[acol + 0][arow] = bv.x;
            Bs[acol + 1][arow] = bv.y;
            Bs[acol + 2][arow] = bv.z;
            Bs[acol + 3][arow] = bv.w;
        } else {
            *(float4*)&Bs[brow][bcol] = *(const float4*)(Bptr + (long long)k0 * ldb);
        }
        __syncthreads();

        #pragma unroll
        for (int kk = 0; kk < 8; kk++) {
            float a[8], b[8];
            *(float4*)&a[0] = *(const float4*)&As[kk][ty * 4];
            *(float4*)&a[4] = *(const float4*)&As[kk][64 + ty * 4];
            *(float4*)&b[0] = *(const float4*)&Bs[kk][tx * 4];
            *(float4*)&b[4] = *(const float4*)&Bs[kk][64 + tx * 4];
            #pragma unroll
            for (int i = 0; i < 8; i++)
                #pragma unroll
                for (int j = 0; j < 8; j++)
                    acc[i][j] += a[i] * b[j];
        }
        __syncthreads();
    }

    #pragma unroll
    for (int ih = 0; ih < 2; ih++) {
        #pragma unroll
        for (int i = 0; i < 4; i++) {
            int row = rowBase + ih * 64 + ty * 4 + i;
            float* cp = C + (long long)row * ldc + colBase;
            int ai = ih * 4 + i;
            float4 v0 = make_float4(acc[ai][0] * alpha, acc[ai][1] * alpha,
                                    acc[ai][2] * alpha, acc[ai][3] * alpha);
            float4 v1 = make_float4(acc[ai][4] * alpha, acc[ai][5] * alpha,
                                    acc[ai][6] * alpha, acc[ai][7] * alpha);
            *(float4*)(cp + tx * 4)      = v0;
            *(float4*)(cp + 64 + tx * 4) = v1;
        }
    }
}

// ---------------------------------------------------------------------------
// Causal softmax, in place on scores. One block per (b,h,s) row.
// ---------------------------------------------------------------------------
__global__ void __launch_bounds__(256)
softmax_kernel(float* __restrict__ sc)
{
    const long long r = blockIdx.x;           // ((b*H+h)*S + s)
    const int s = (int)(r & (S_ - 1));
    const int L = s + 1;
    float* row = sc + r * S_;
    const int tid = threadIdx.x;
    __shared__ float red[256];

    float vals[4];
    float mx = -FLT_MAX;
    #pragma unroll
    for (int c = 0; c < 4; c++) {
        int t = tid + c * 256;
        float v = (t < L) ? row[t] : -FLT_MAX;
        vals[c] = v;
        mx = fmaxf(mx, v);
    }
    red[tid] = mx; __syncthreads();
    #pragma unroll
    for (int o = 128; o > 0; o >>= 1) { if (tid < o) red[tid] = fmaxf(red[tid], red[tid + o]); __syncthreads(); }
    mx = red[0]; __syncthreads();

    float sum = 0.f;
    #pragma unroll
    for (int c = 0; c < 4; c++) {
        int t = tid + c * 256;
        float e = (t < L) ? expf(vals[c] - mx) : 0.f;
        vals[c] = e;
        sum += e;
    }
    red[tid] = sum; __syncthreads();
    #pragma unroll
    for (int o = 128; o > 0; o >>= 1) { if (tid < o) red[tid] += red[tid + o]; __syncthreads(); }
    const float inv = 1.0f / red[0];

    #pragma unroll
    for (int c = 0; c < 4; c++) {
        int t = tid + c * 256;
        row[t] = vals[c] * inv;
    }
}

// ---------------------------------------------------------------------------
// GeGLU elementwise: G = gelu_exact(G) * U
// ---------------------------------------------------------------------------
__global__ void __launch_bounds__(256)
geglu_kernel(float* __restrict__ G, const float* __restrict__ U)
{
    const long long i = ((long long)blockIdx.x * 256 + threadIdx.x) * 4;
    float4 g = *(const float4*)(G + i);
    float4 u = *(const float4*)(U + i);
    const float c = 0.70710678118654752f;
    g.x = 0.5f * g.x * (1.f + erff(g.x * c)) * u.x;
    g.y = 0.5f * g.y * (1.f + erff(g.y * c)) * u.y;
    g.z = 0.5f * g.z * (1.f + erff(g.z * c)) * u.z;
    g.w = 0.5f * g.w * (1.f + erff(g.w * c)) * u.w;
    *(float4*)(G + i) = g;
}

// ---------------------------------------------------------------------------
// Host launch
// ---------------------------------------------------------------------------
extern "C" void kernel_launch(void* const* d_in, const int* in_sizes, int n_in,
                              void* d_out, int out_size)
{
    const float* x      = (const float*)d_in[0];
    const float* gamma1 = (const float*)d_in[1];
    const float* beta1  = (const float*)d_in[2];
    const float* Wq     = (const float*)d_in[3];
    const float* Wk     = (const float*)d_in[4];
    const float* Wv     = (const float*)d_in[5];
    const float* Wo     = (const float*)d_in[6];
    const float* gamma2 = (const float*)d_in[7];
    const float* beta2  = (const float*)d_in[8];
    const float* Wg     = (const float*)d_in[9];
    const float* Wu     = (const float*)d_in[10];
    const float* Wd     = (const float*)d_in[11];
    float* out = (float*)d_out;

    float *y, *yp, *q, *k, *v, *sc, *ctx, *attn, *z, *G, *U;
    cudaGetSymbolAddress((void**)&y,    g_y);
    cudaGetSymbolAddress((void**)&yp,   g_yp);
    cudaGetSymbolAddress((void**)&q,    g_q);
    cudaGetSymbolAddress((void**)&k,    g_k);
    cudaGetSymbolAddress((void**)&v,    g_v);
    cudaGetSymbolAddress((void**)&sc,   g_sc);
    cudaGetSymbolAddress((void**)&ctx,  g_ctx);
    cudaGetSymbolAddress((void**)&attn, g_attn);
    cudaGetSymbolAddress((void**)&z,    g_z);
    cudaGetSymbolAddress((void**)&G,    g_G);
    cudaGetSymbolAddress((void**)&U,    g_U);

    const float qscale = 0.08838834764831845f;   // DH^-0.5

    // 1. LN1 + RoPE
    ln_kernel<true><<<M_, 256>>>(x, gamma1, beta1, y, yp);

    // 2-4. QKV projections (M=4096, N=2048, K=2048), NN
    {
        dim3 g(E_ / 128, M_ / 128, 1);
        sgemm_kernel<false,false><<<g, 256>>>(yp, Wq, q, E_, E_, E_, E_,
            0,0, 0,0, 0,0, 1, qscale);
        sgemm_kernel<false,false><<<g, 256>>>(yp, Wk, k, E_, E_, E_, E_,
            0,0, 0,0, 0,0, 1, 1.0f);
        sgemm_kernel<false,false><<<g, 256>>>(y,  Wv, v, E_, E_, E_, E_,
            0,0, 0,0, 0,0, 1, 1.0f);
    }

    // 5. scores = q @ k^T  (batched over B*H, NT, causal tile skip)
    {
        dim3 g(S_ / 128, S_ / 128, B_ * H_);
        const long long sQb = (long long)S_ * H_ * DH_, sQh = DH_;
        const long long sSb = (long long)H_ * S_ * S_,  sSh = (long long)S_ * S_;
        sgemm_kernel<true,true><<<g, 256>>>(q, k, sc, DH_,
            H_ * DH_, H_ * DH_, S_,
            sQb, sQh, sQb, sQh, sSb, sSh, H_, 1.0f);
    }

    // 6. causal softmax in place
    softmax_kernel<<<B_ * H_ * S_, 256>>>(sc);

    // 7. ctx = probs @ v  (batched NN)
    {
        dim3 g(DH_ / 128, S_ / 128, B_ * H_);
        const long long sSb = (long long)H_ * S_ * S_,  sSh = (long long)S_ * S_;
        const long long sVb = (long long)S_ * H_ * DH_, sVh = DH_;
        sgemm_kernel<false,false><<<g, 256>>>(sc, v, ctx, S_,
            S_, H_ * DH_, H_ * DH_,
            sSb, sSh, sVb, sVh, sVb, sVh, H_, 1.0f);
    }

    // 8. attn = ctx @ Wo  (Wo is [H*DH, E] with K index h*DH+d)
    {
        dim3 g(E_ / 128, M_ / 128, 1);
        sgemm_kernel<false,false><<<g, 256>>>(ctx, Wo, attn, E_, E_, E_, E_,
            0,0, 0,0, 0,0, 1, 1.0f);
    }

    // 9. LN2
    ln_kernel<false><<<M_, 256>>>(attn, gamma2, beta2, z, nullptr);

    // 10-11. gate / up projections (M=4096, N=8192, K=2048)
    {
        dim3 g(F_ / 128, M_ / 128, 1);
        sgemm_kernel<false,false><<<g, 256>>>(z, Wg, G, E_, E_, F_, F_,
            0,0, 0,0, 0,0, 1, 1.0f);
        sgemm_kernel<false,false><<<g, 256>>>(z, Wu, U, E_, E_, F_, F_,
            0,0, 0,0, 0,0, 1, 1.0f);
    }

    // 12. GeGLU elementwise (in place into G)
    {
        long long n = (long long)M_ * F_;
        geglu_kernel<<<(unsigned)(n / (256 * 4)), 256>>>(G, U);
    }

    // 13. out = G @ Wd  (M=4096, N=2048, K=8192)
    {
        dim3 g(E_ / 128, M_ / 128, 1);
        sgemm_kernel<false,false><<<g, 256>>>(G, Wd, out, F_, F_, E_, E_,
            0,0, 0,0, 0,0, 1, 1.0f);
    }
}

// round 9
// speedup vs baseline: 1.4968x; 1.4968x over previous
#include <cuda_runtime.h>
#include <cuda_bf16.h>
#include <cstdint>
#include <math.h>
#include <float.h>

// Problem constants
#define B_  4
#define S_  1024
#define E_  2048
#define H_  16
#define DH_ 128
#define F_  8192
#define M_  (B_ * S_)          // 4096 rows

// ---------------------------------------------------------------------------
// Scratch (device globals; allocation-free contract)
// ---------------------------------------------------------------------------
__device__ float g_y   [(size_t)M_ * E_];
__device__ float g_yp  [(size_t)M_ * E_];
__device__ float g_q   [(size_t)M_ * E_];
__device__ float g_k   [(size_t)M_ * E_];
__device__ float g_v   [(size_t)M_ * E_];
__device__ float g_vT  [(size_t)M_ * E_];           // [B,H,DH,S]
__device__ float g_sc  [(size_t)B_ * H_ * S_ * S_]; // scores/probs
__device__ float g_ctx [(size_t)M_ * E_];
__device__ float g_attn[(size_t)M_ * E_];
__device__ float g_z   [(size_t)M_ * E_];
__device__ float g_G   [(size_t)M_ * F_];
__device__ float g_U   [(size_t)M_ * F_];
// transposed weights (Bt layout: [N][K], K contiguous)
__device__ float g_WqT [(size_t)E_ * E_];
__device__ float g_WkT [(size_t)E_ * E_];
__device__ float g_WvT [(size_t)E_ * E_];
__device__ float g_WoT [(size_t)E_ * E_];
__device__ float g_WgT [(size_t)F_ * E_];
__device__ float g_WuT [(size_t)F_ * E_];
__device__ float g_WdT [(size_t)E_ * F_];

// ---------------------------------------------------------------------------
// PTX helpers (baseline ISA only: cp.async + mma.sync bf16)
// ---------------------------------------------------------------------------
__device__ __forceinline__ uint32_t smem_u32(const void* p) {
    uint32_t a;
    asm("{ .reg .u64 t; cvta.to.shared.u64 t, %1; cvt.u32.u64 %0, t; }"
        : "=r"(a) : "l"(p));
    return a;
}

__device__ __forceinline__ void cp_async16(uint32_t dst, const void* src) {
    asm volatile("cp.async.cg.shared.global [%0], [%1], 16;"
                 :: "r"(dst), "l"(src) : "memory");
}
__device__ __forceinline__ void cp_commit() {
    asm volatile("cp.async.commit_group;" ::: "memory");
}
template<int N> __device__ __forceinline__ void cp_wait() {
    asm volatile("cp.async.wait_group %0;" :: "n"(N) : "memory");
}

// split f32 pair into packed bf16x2 (hi) + packed bf16x2 (lo residual)
__device__ __forceinline__ void split2(float f0, float f1, uint32_t& hi, uint32_t& lo) {
    __nv_bfloat162 h = __floats2bfloat162_rn(f0, f1);   // x=f0, y=f1
    float h0 = __bfloat162float(__low2bfloat16(h));
    float h1 = __bfloat162float(__high2bfloat16(h));
    __nv_bfloat162 l = __floats2bfloat162_rn(f0 - h0, f1 - h1);
    hi = *reinterpret_cast<uint32_t*>(&h);
    lo = *reinterpret_cast<uint32_t*>(&l);
}

__device__ __forceinline__ void mma_bf16(float* c, const uint32_t* a, const uint32_t* b) {
    asm volatile(
        "mma.sync.aligned.m16n8k16.row.col.f32.bf16.bf16.f32 "
        "{%0,%1,%2,%3}, {%4,%5,%6,%7}, {%8,%9}, {%0,%1,%2,%3};"
        : "+f"(c[0]), "+f"(c[1]), "+f"(c[2]), "+f"(c[3])
        : "r"(a[0]), "r"(a[1]), "r"(a[2]), "r"(a[3]), "r"(b[0]), "r"(b[1]));
}

// ---------------------------------------------------------------------------
// Split-bf16 mma.sync GEMM: C[M,N] = alpha * A[M,K] * Bt[N,K]^T
// (near-fp32 accuracy: hi*hi + hi*lo + lo*hi, fp32 accumulate)
// CTA tile 128x128, K-stage 32, cp.async double-buffered, 8 warps (2x4).
// smem tiles padded to stride 36 floats.
// Batched via z: b = z/Hdiv, h = z%Hdiv, per-operand (b,h) strides.
// ---------------------------------------------------------------------------
#define TSTR 36                     // padded row stride (floats)
#define TILE_F (128 * TSTR)         // floats per tile buffer

template<bool CAUSAL>
__global__ void __launch_bounds__(256)
mma_gemm(const float* __restrict__ A, const float* __restrict__ Bt,
         float* __restrict__ C,
         int K, int lda, int ldb, int ldc,
         long long sAb, long long sAh,
         long long sBb, long long sBh,
         long long sCb, long long sCh,
         int Hdiv, float alpha)
{
    if (CAUSAL && blockIdx.x > blockIdx.y) return;
    const int rowBase = blockIdx.y * 128;
    const int colBase = blockIdx.x * 128;

    const int z  = blockIdx.z;
    const int bb = z / Hdiv;
    const int hh = z - bb * Hdiv;
    A  += bb * sAb + hh * sAh;
    Bt += bb * sBb + hh * sBh;
    C  += bb * sCb + hh * sCh;

    extern __shared__ float smem[];
    float* AsBuf[2] = { smem,              smem + TILE_F };
    float* BsBuf[2] = { smem + 2 * TILE_F, smem + 3 * TILE_F };
    uint32_t asU[2] = { smem_u32(AsBuf[0]), smem_u32(AsBuf[1]) };
    uint32_t bsU[2] = { smem_u32(BsBuf[0]), smem_u32(BsBuf[1]) };

    const int tid   = threadIdx.x;
    const int lane  = tid & 31;
    const int wid   = tid >> 5;
    const int warpM = wid >> 2;       // 0..1
    const int warpN = wid & 3;        // 0..3

    float acc[4][4][4];
    #pragma unroll
    for (int mi = 0; mi < 4; mi++)
        #pragma unroll
        for (int ni = 0; ni < 4; ni++)
            #pragma unroll
            for (int r = 0; r < 4; r++) acc[mi][ni][r] = 0.f;

    const int KT = K >> 5;

    // tile loader: 128 rows x 32 floats = 1024 float4, 4 per thread
    auto load_tiles = [&](int kt, int buf) {
        const float* Ab = A + (long long)rowBase * lda + kt * 32;
        const float* Bb = Bt + (long long)colBase * ldb + kt * 32;
        #pragma unroll
        for (int i = 0; i < 4; i++) {
            int idx = tid + i * 256;
            int r = idx >> 3, c = idx & 7;
            cp_async16(asU[buf] + (uint32_t)(r * TSTR + c * 4) * 4,
                       Ab + (long long)r * lda + c * 4);
        }
        #pragma unroll
        for (int i = 0; i < 4; i++) {
            int idx = tid + i * 256;
            int r = idx >> 3, c = idx & 7;
            cp_async16(bsU[buf] + (uint32_t)(r * TSTR + c * 4) * 4,
                       Bb + (long long)r * ldb + c * 4);
        }
        cp_commit();
    };

    load_tiles(0, 0);

    for (int kt = 0; kt < KT; kt++) {
        const int buf = kt & 1;
        if (kt + 1 < KT) {
            load_tiles(kt + 1, buf ^ 1);
            cp_wait<1>();
        } else {
            cp_wait<0>();
        }
        __syncthreads();

        const float* as = AsBuf[buf];
        const float* bs = BsBuf[buf];

        #pragma unroll
        for (int ks = 0; ks < 2; ks++) {      // two k16 steps per 32-K stage
            uint32_t ahi[4][4], alo[4][4], bhi[4][2], blo[4][2];
            const int arow = warpM * 64 + (lane >> 2);
            const int kb   = ks * 16 + (lane & 3) * 2;
            #pragma unroll
            for (int mi = 0; mi < 4; mi++) {
                const float* ap = as + (arow + mi * 16) * TSTR + kb;
                float2 p0 = *(const float2*)(ap);                 // (row,   k..k+1)
                float2 p1 = *(const float2*)(ap + 8);             // (row,   k+8..)
                float2 p2 = *(const float2*)(ap + 8 * TSTR);      // (row+8, k..k+1)
                float2 p3 = *(const float2*)(ap + 8 * TSTR + 8);  // (row+8, k+8..)
                split2(p0.x, p0.y, ahi[mi][0], alo[mi][0]);
                split2(p2.x, p2.y, ahi[mi][1], alo[mi][1]);
                split2(p1.x, p1.y, ahi[mi][2], alo[mi][2]);
                split2(p3.x, p3.y, ahi[mi][3], alo[mi][3]);
            }
            const int brow = warpN * 32 + (lane >> 2);
            #pragma unroll
            for (int ni = 0; ni < 4; ni++) {
                const float* bp = bs + (brow + ni * 8) * TSTR + kb;
                float2 q0 = *(const float2*)(bp);
                float2 q1 = *(const float2*)(bp + 8);
                split2(q0.x, q0.y, bhi[ni][0], blo[ni][0]);
                split2(q1.x, q1.y, bhi[ni][1], blo[ni][1]);
            }
            #pragma unroll
            for (int mi = 0; mi < 4; mi++)
                #pragma unroll
                for (int ni = 0; ni < 4; ni++) {
                    mma_bf16(acc[mi][ni], ahi[mi], bhi[ni]);
                    mma_bf16(acc[mi][ni], ahi[mi], blo[ni]);
                    mma_bf16(acc[mi][ni], alo[mi], bhi[ni]);
                }
        }
        __syncthreads();
    }

    // epilogue (m16n8 C fragment layout)
    const int r0 = rowBase + warpM * 64 + (lane >> 2);
    const int c0 = colBase + warpN * 32 + (lane & 3) * 2;
    #pragma unroll
    for (int mi = 0; mi < 4; mi++) {
        #pragma unroll
        for (int ni = 0; ni < 4; ni++) {
            const int row = r0 + mi * 16;
            const int col = c0 + ni * 8;
            float2 v0 = make_float2(acc[mi][ni][0] * alpha, acc[mi][ni][1] * alpha);
            float2 v1 = make_float2(acc[mi][ni][2] * alpha, acc[mi][ni][3] * alpha);
            *(float2*)(C + (long long)row * ldc + col)       = v0;
            *(float2*)(C + (long long)(row + 8) * ldc + col) = v1;
        }
    }
}

// ---------------------------------------------------------------------------
// Tiled transpose: dst[c][r] = src[r][c], batched via z (b,h split)
// grid (C/32, R/32, Z), block (32, 8)
// ---------------------------------------------------------------------------
__global__ void __launch_bounds__(256)
transpose_kernel(const float* __restrict__ src, float* __restrict__ dst,
                 int ldS, int ldD,
                 long long sSb, long long sSh, long long sDb, long long sDh,
                 int Hdiv)
{
    __shared__ float t[32][33];
    const int z = blockIdx.z, bb = z / Hdiv, hh = z - bb * Hdiv;
    src += bb * sSb + hh * sSh;
    dst += bb * sDb + hh * sDh;
    const int c0 = blockIdx.x * 32, r0 = blockIdx.y * 32;
    const int x = threadIdx.x, y = threadIdx.y;
    #pragma unroll
    for (int j = 0; j < 32; j += 8)
        t[y + j][x] = src[(long long)(r0 + y + j) * ldS + c0 + x];
    __syncthreads();
    #pragma unroll
    for (int j = 0; j < 32; j += 8)
        dst[(long long)(c0 + y + j) * ldD + r0 + x] = t[x][y + j];
}

// ---------------------------------------------------------------------------
// LayerNorm (+ optional RoPE) — one block per row
// ---------------------------------------------------------------------------
template<bool ROPE>
__global__ void __launch_bounds__(256)
ln_kernel(const float* __restrict__ x,
          const float* __restrict__ gamma, const float* __restrict__ beta,
          float* __restrict__ y, float* __restrict__ yp)
{
    __shared__ float sy[E_];
    __shared__ float red[256];
    const int r   = blockIdx.x;
    const int s   = r & (S_ - 1);
    const int tid = threadIdx.x;
    const float* xr = x + (long long)r * E_;

    float sum = 0.f;
    #pragma unroll
    for (int i = tid; i < E_; i += 256) { float v = xr[i]; sy[i] = v; sum += v; }
    red[tid] = sum; __syncthreads();
    #pragma unroll
    for (int o = 128; o > 0; o >>= 1) { if (tid < o) red[tid] += red[tid + o]; __syncthreads(); }
    const float mean = red[0] * (1.0f / E_);
    __syncthreads();

    float vs = 0.f;
    #pragma unroll
    for (int i = tid; i < E_; i += 256) { float d = sy[i] - mean; vs += d * d; }
    red[tid] = vs; __syncthreads();
    #pragma unroll
    for (int o = 128; o > 0; o >>= 1) { if (tid < o) red[tid] += red[tid + o]; __syncthreads(); }
    const float rstd = rsqrtf(red[0] * (1.0f / E_) + 1e-6f);
    __syncthreads();

    #pragma unroll
    for (int i = tid; i < E_; i += 256) {
        float v = (sy[i] - mean) * rstd * gamma[i] + beta[i];
        y[(long long)r * E_ + i] = v;
        sy[i] = v;
    }
    if (ROPE) {
        __syncthreads();
        const float l2c = 13.287712379549449f / 1024.0f;
        #pragma unroll
        for (int i = tid; i < E_; i += 256) {
            int j = (i < 1024) ? i : (i - 1024);
            float ang = (float)s * exp2f(-(float)j * l2c);
            float c, sn;
            sincosf(ang, &sn, &c);
            float rot = (i < 1024) ? -sy[i + 1024] : sy[i - 1024];
            yp[(long long)r * E_ + i] = sy[i] * c + rot * sn;
        }
    }
}

// ---------------------------------------------------------------------------
// Causal softmax, in place. One block per (b,h,s) row.
// ---------------------------------------------------------------------------
__global__ void __launch_bounds__(256)
softmax_kernel(float* __restrict__ sc)
{
    const long long r = blockIdx.x;
    const int s = (int)(r & (S_ - 1));
    const int L = s + 1;
    float* row = sc + r * S_;
    const int tid = threadIdx.x;
    __shared__ float red[256];

    float vals[4];
    float mx = -FLT_MAX;
    #pragma unroll
    for (int c = 0; c < 4; c++) {
        int t = tid + c * 256;
        float v = (t < L) ? row[t] : -FLT_MAX;
        vals[c] = v;
        mx = fmaxf(mx, v);
    }
    red[tid] = mx; __syncthreads();
    #pragma unroll
    for (int o = 128; o > 0; o >>= 1) { if (tid < o) red[tid] = fmaxf(red[tid], red[tid + o]); __syncthreads(); }
    mx = red[0]; __syncthreads();

    float sum = 0.f;
    #pragma unroll
    for (int c = 0; c < 4; c++) {
        int t = tid + c * 256;
        float e = (t < L) ? expf(vals[c] - mx) : 0.f;
        vals[c] = e;
        sum += e;
    }
    red[tid] = sum; __syncthreads();
    #pragma unroll
    for (int o = 128; o > 0; o >>= 1) { if (tid < o) red[tid] += red[tid + o]; __syncthreads(); }
    const float inv = 1.0f / red[0];

    #pragma unroll
    for (int c = 0; c < 4; c++) {
        int t = tid + c * 256;
        row[t] = vals[c] * inv;
    }
}

// ---------------------------------------------------------------------------
// GeGLU elementwise: G = gelu_exact(G) * U
// ---------------------------------------------------------------------------
__global__ void __launch_bounds__(256)
geglu_kernel(float* __restrict__ G, const float* __restrict__ U)
{
    const long long i = ((long long)blockIdx.x * 256 + threadIdx.x) * 4;
    float4 g = *(const float4*)(G + i);
    float4 u = *(const float4*)(U + i);
    const float c = 0.70710678118654752f;
    g.x = 0.5f * g.x * (1.f + erff(g.x * c)) * u.x;
    g.y = 0.5f * g.y * (1.f + erff(g.y * c)) * u.y;
    g.z = 0.5f * g.z * (1.f + erff(g.z * c)) * u.z;
    g.w = 0.5f * g.w * (1.f + erff(g.w * c)) * u.w;
    *(float4*)(G + i) = g;
}

// ---------------------------------------------------------------------------
// Host launch
// ---------------------------------------------------------------------------
extern "C" void kernel_launch(void* const* d_in, const int* in_sizes, int n_in,
                              void* d_out, int out_size)
{
    const float* x      = (const float*)d_in[0];
    const float* gamma1 = (const float*)d_in[1];
    const float* beta1  = (const float*)d_in[2];
    const float* Wq     = (const float*)d_in[3];
    const float* Wk     = (const float*)d_in[4];
    const float* Wv     = (const float*)d_in[5];
    const float* Wo     = (const float*)d_in[6];
    const float* gamma2 = (const float*)d_in[7];
    const float* beta2  = (const float*)d_in[8];
    const float* Wg     = (const float*)d_in[9];
    const float* Wu     = (const float*)d_in[10];
    const float* Wd     = (const float*)d_in[11];
    float* out = (float*)d_out;

    float *y, *yp, *q, *k, *v, *vT, *sc, *ctx, *attn, *z, *G, *U;
    float *WqT, *WkT, *WvT, *WoT, *WgT, *WuT, *WdT;
    cudaGetSymbolAddress((void**)&y,    g_y);
    cudaGetSymbolAddress((void**)&yp,   g_yp);
    cudaGetSymbolAddress((void**)&q,    g_q);
    cudaGetSymbolAddress((void**)&k,    g_k);
    cudaGetSymbolAddress((void**)&v,    g_v);
    cudaGetSymbolAddress((void**)&vT,   g_vT);
    cudaGetSymbolAddress((void**)&sc,   g_sc);
    cudaGetSymbolAddress((void**)&ctx,  g_ctx);
    cudaGetSymbolAddress((void**)&attn, g_attn);
    cudaGetSymbolAddress((void**)&z,    g_z);
    cudaGetSymbolAddress((void**)&G,    g_G);
    cudaGetSymbolAddress((void**)&U,    g_U);
    cudaGetSymbolAddress((void**)&WqT,  g_WqT);
    cudaGetSymbolAddress((void**)&WkT,  g_WkT);
    cudaGetSymbolAddress((void**)&WvT,  g_WvT);
    cudaGetSymbolAddress((void**)&WoT,  g_WoT);
    cudaGetSymbolAddress((void**)&WgT,  g_WgT);
    cudaGetSymbolAddress((void**)&WuT,  g_WuT);
    cudaGetSymbolAddress((void**)&WdT,  g_WdT);

    const int SMEM = 4 * TILE_F * 4;   // 73728 bytes
    cudaFuncSetAttribute(mma_gemm<false>, cudaFuncAttributeMaxDynamicSharedMemorySize, SMEM);
    cudaFuncSetAttribute(mma_gemm<true>,  cudaFuncAttributeMaxDynamicSharedMemorySize, SMEM);

    const float qscale = 0.08838834764831845f;   // DH^-0.5
    const dim3 tb(32, 8);

    // 0. weight transposes (Bt layout [N][K])
    transpose_kernel<<<dim3(64, 64, 1),  tb>>>(Wq, WqT, E_, E_, 0,0, 0,0, 1);
    transpose_kernel<<<dim3(64, 64, 1),  tb>>>(Wk, WkT, E_, E_, 0,0, 0,0, 1);
    transpose_kernel<<<dim3(64, 64, 1),  tb>>>(Wv, WvT, E_, E_, 0,0, 0,0, 1);
    transpose_kernel<<<dim3(64, 64, 1),  tb>>>(Wo, WoT, E_, E_, 0,0, 0,0, 1);
    transpose_kernel<<<dim3(256, 64, 1), tb>>>(Wg, WgT, F_, E_, 0,0, 0,0, 1);
    transpose_kernel<<<dim3(256, 64, 1), tb>>>(Wu, WuT, F_, E_, 0,0, 0,0, 1);
    transpose_kernel<<<dim3(64, 256, 1), tb>>>(Wd, WdT, E_, F_, 0,0, 0,0, 1);

    // 1. LN1 + RoPE
    ln_kernel<true><<<M_, 256>>>(x, gamma1, beta1, y, yp);

    // 2-4. QKV projections: [4096,2048] x [2048,2048]^T
    {
        dim3 g(E_ / 128, M_ / 128, 1);
        mma_gemm<false><<<g, 256, SMEM>>>(yp, WqT, q, E_, E_, E_, E_,
            0,0, 0,0, 0,0, 1, qscale);
        mma_gemm<false><<<g, 256, SMEM>>>(yp, WkT, k, E_, E_, E_, E_,
            0,0, 0,0, 0,0, 1, 1.0f);
        mma_gemm<false><<<g, 256, SMEM>>>(y,  WvT, v, E_, E_, E_, E_,
            0,0, 0,0, 0,0, 1, 1.0f);
    }

    // 4b. transpose v -> vT [B,H,DH,S]
    transpose_kernel<<<dim3(DH_ / 32, S_ / 32, B_ * H_), tb>>>(
        v, vT, E_, S_,
        (long long)S_ * E_, (long long)DH_,
        (long long)H_ * DH_ * S_, (long long)DH_ * S_, H_);

    // 5. scores = q @ k^T (batched over B*H, causal tile skip)
    {
        dim3 g(S_ / 128, S_ / 128, B_ * H_);
        const long long sQb = (long long)S_ * E_, sQh = DH_;
        const long long sSb = (long long)H_ * S_ * S_, sSh = (long long)S_ * S_;
        mma_gemm<true><<<g, 256, SMEM>>>(q, k, sc, DH_,
            E_, E_, S_, sQb, sQh, sQb, sQh, sSb, sSh, H_, 1.0f);
    }

    // 6. causal softmax
    softmax_kernel<<<B_ * H_ * S_, 256>>>(sc);

    // 7. ctx = probs @ v  (Bt = vT)
    {
        dim3 g(DH_ / 128, S_ / 128, B_ * H_);
        const long long sSb = (long long)H_ * S_ * S_, sSh = (long long)S_ * S_;
        const long long sVb = (long long)H_ * DH_ * S_, sVh = (long long)DH_ * S_;
        const long long sCb = (long long)S_ * E_, sCh = DH_;
        mma_gemm<false><<<g, 256, SMEM>>>(sc, vT, ctx, S_,
            S_, S_, E_, sSb, sSh, sVb, sVh, sCb, sCh, H_, 1.0f);
    }

    // 8. attn = ctx @ Wo
    {
        dim3 g(E_ / 128, M_ / 128, 1);
        mma_gemm<false><<<g, 256, SMEM>>>(ctx, WoT, attn, E_, E_, E_, E_,
            0,0, 0,0, 0,0, 1, 1.0f);
    }

    // 9. LN2
    ln_kernel<false><<<M_, 256>>>(attn, gamma2, beta2, z, nullptr);

    // 10-11. gate / up: [4096,2048] x [8192,2048]^T
    {
        dim3 g(F_ / 128, M_ / 128, 1);
        mma_gemm<false><<<g, 256, SMEM>>>(z, WgT, G, E_, E_, E_, F_,
            0,0, 0,0, 0,0, 1, 1.0f);
        mma_gemm<false><<<g, 256, SMEM>>>(z, WuT, U, E_, E_, E_, F_,
            0,0, 0,0, 0,0, 1, 1.0f);
    }

    // 12. GeGLU elementwise
    {
        long long n = (long long)M_ * F_;
        geglu_kernel<<<(unsigned)(n / (256 * 4)), 256>>>(G, U);
    }

    // 13. out = G @ Wd : [4096,8192] x [2048,8192]^T
    {
        dim3 g(E_ / 128, M_ / 128, 1);
        mma_gemm<false><<<g, 256, SMEM>>>(G, WdT, out, F_, F_, F_, E_,
            0,0, 0,0, 0,0, 1, 1.0f);
    }
}

// round 10
// speedup vs baseline: 2.1942x; 1.4660x over previous
#include <cuda_runtime.h>
#include <cuda_bf16.h>
#include <cstdint>
#include <math.h>
#include <float.h>

// Problem constants
#define B_  4
#define S_  1024
#define E_  2048
#define H_  16
#define DH_ 128
#define F_  8192
#define M_  (B_ * S_)          // 4096 rows

typedef __nv_bfloat16 bf16;

// ---------------------------------------------------------------------------
// Scratch (device globals; allocation-free contract)
// ---------------------------------------------------------------------------
// fp32 intermediates (where the next consumer needs fp32)
__device__ float g_v   [(size_t)M_ * E_];
__device__ float g_sc  [(size_t)B_ * H_ * S_ * S_]; // raw scores
__device__ float g_attn[(size_t)M_ * E_];
__device__ float g_G   [(size_t)M_ * F_];
__device__ float g_U   [(size_t)M_ * F_];
// split (hi/lo bf16) operands for GEMMs
__device__ bf16 g_y_hi [(size_t)M_ * E_];
__device__ bf16 g_y_lo [(size_t)M_ * E_];
__device__ bf16 g_yp_hi[(size_t)M_ * E_];
__device__ bf16 g_yp_lo[(size_t)M_ * E_];
__device__ bf16 g_q_hi [(size_t)M_ * E_];
__device__ bf16 g_q_lo [(size_t)M_ * E_];
__device__ bf16 g_k_hi [(size_t)M_ * E_];
__device__ bf16 g_k_lo [(size_t)M_ * E_];
__device__ bf16 g_vT_hi[(size_t)M_ * E_];           // [B,H,DH,S]
__device__ bf16 g_vT_lo[(size_t)M_ * E_];
__device__ bf16 g_p_hi [(size_t)B_ * H_ * S_ * S_]; // probs
__device__ bf16 g_p_lo [(size_t)B_ * H_ * S_ * S_];
__device__ bf16 g_ctx_hi[(size_t)M_ * E_];
__device__ bf16 g_ctx_lo[(size_t)M_ * E_];
__device__ bf16 g_z_hi [(size_t)M_ * E_];
__device__ bf16 g_z_lo [(size_t)M_ * E_];
__device__ bf16 g_gg_hi[(size_t)M_ * F_];           // gelu(G)*U
__device__ bf16 g_gg_lo[(size_t)M_ * F_];
// transposed, split weights (Bt layout: [N][K], K contiguous)
__device__ bf16 g_WqT_hi[(size_t)E_ * E_];  __device__ bf16 g_WqT_lo[(size_t)E_ * E_];
__device__ bf16 g_WkT_hi[(size_t)E_ * E_];  __device__ bf16 g_WkT_lo[(size_t)E_ * E_];
__device__ bf16 g_WvT_hi[(size_t)E_ * E_];  __device__ bf16 g_WvT_lo[(size_t)E_ * E_];
__device__ bf16 g_WoT_hi[(size_t)E_ * E_];  __device__ bf16 g_WoT_lo[(size_t)E_ * E_];
__device__ bf16 g_WgT_hi[(size_t)F_ * E_];  __device__ bf16 g_WgT_lo[(size_t)F_ * E_];
__device__ bf16 g_WuT_hi[(size_t)F_ * E_];  __device__ bf16 g_WuT_lo[(size_t)F_ * E_];
__device__ bf16 g_WdT_hi[(size_t)E_ * F_];  __device__ bf16 g_WdT_lo[(size_t)E_ * F_];

// ---------------------------------------------------------------------------
// PTX helpers
// ---------------------------------------------------------------------------
__device__ __forceinline__ uint32_t smem_u32(const void* p) {
    uint32_t a;
    asm("{ .reg .u64 t; cvta.to.shared.u64 t, %1; cvt.u32.u64 %0, t; }"
        : "=r"(a) : "l"(p));
    return a;
}
__device__ __forceinline__ void cp_async16(uint32_t dst, const void* src) {
    asm volatile("cp.async.cg.shared.global [%0], [%1], 16;"
                 :: "r"(dst), "l"(src) : "memory");
}
__device__ __forceinline__ void cp_commit() {
    asm volatile("cp.async.commit_group;" ::: "memory");
}
template<int N> __device__ __forceinline__ void cp_wait() {
    asm volatile("cp.async.wait_group %0;" :: "n"(N) : "memory");
}

// split f32 pair into packed bf16x2 (hi) + packed bf16x2 (lo residual)
__device__ __forceinline__ void split2(float f0, float f1, uint32_t& hi, uint32_t& lo) {
    __nv_bfloat162 h = __floats2bfloat162_rn(f0, f1);
    float h0 = __bfloat162float(__low2bfloat16(h));
    float h1 = __bfloat162float(__high2bfloat16(h));
    __nv_bfloat162 l = __floats2bfloat162_rn(f0 - h0, f1 - h1);
    hi = *reinterpret_cast<uint32_t*>(&h);
    lo = *reinterpret_cast<uint32_t*>(&l);
}

__device__ __forceinline__ void mma_bf16(float* c, const uint32_t* a, const uint32_t* b) {
    asm volatile(
        "mma.sync.aligned.m16n8k16.row.col.f32.bf16.bf16.f32 "
        "{%0,%1,%2,%3}, {%4,%5,%6,%7}, {%8,%9}, {%0,%1,%2,%3};"
        : "+f"(c[0]), "+f"(c[1]), "+f"(c[2]), "+f"(c[3])
        : "r"(a[0]), "r"(a[1]), "r"(a[2]), "r"(a[3]), "r"(b[0]), "r"(b[1]));
}

// ---------------------------------------------------------------------------
// Pre-split bf16 GEMM: C = alpha * (Ahi+Alo)[M,K] * ((Bhi+Blo)[N,K])^T
// 3-term: hi*hi + hi*lo + lo*hi, fp32 accumulate. CTA tile 128x128, K-stage 32,
// cp.async double-buffered, 8 warps (2x4). smem bf16 tiles, row stride 40
// (20 u32: (20*row+c) mod 32 hits all banks -> conflict-free 32-bit LDS).
// SPLIT_OUT: epilogue writes hi/lo bf16 arrays instead of fp32 C.
// ---------------------------------------------------------------------------
#define BSTR  40                    // bf16 elems per smem row
#define TILEB (128 * BSTR)          // bf16 elems per tile (5120)

template<bool CAUSAL, bool SPLIT_OUT>
__global__ void __launch_bounds__(256, 2)
mma_gemm(const bf16* __restrict__ Ahi, const bf16* __restrict__ Alo,
         const bf16* __restrict__ Bhi, const bf16* __restrict__ Blo,
         float* __restrict__ C, bf16* __restrict__ Chi, bf16* __restrict__ Clo,
         int K, int lda, int ldb, int ldc,
         long long sAb, long long sAh,
         long long sBb, long long sBh,
         long long sCb, long long sCh,
         int Hdiv, float alpha)
{
    if (CAUSAL && blockIdx.x > blockIdx.y) return;
    const int rowBase = blockIdx.y * 128;
    const int colBase = blockIdx.x * 128;

    const int z  = blockIdx.z;
    const int bb = z / Hdiv;
    const int hh = z - bb * Hdiv;
    const long long offA = bb * sAb + hh * sAh;
    const long long offB = bb * sBb + hh * sBh;
    const long long offC = bb * sCb + hh * sCh;
    Ahi += offA; Alo += offA;
    Bhi += offB; Blo += offB;

    extern __shared__ bf16 smem[];
    const uint32_t smemU = smem_u32(smem);

    const int tid   = threadIdx.x;
    const int lane  = tid & 31;
    const int wid   = tid >> 5;
    const int warpM = wid >> 2;       // 0..1
    const int warpN = wid & 3;        // 0..3

    float acc[4][4][4];
    #pragma unroll
    for (int mi = 0; mi < 4; mi++)
        #pragma unroll
        for (int ni = 0; ni < 4; ni++)
            #pragma unroll
            for (int r = 0; r < 4; r++) acc[mi][ni][r] = 0.f;

    const int KT = K >> 5;
    const int lr = tid >> 2;          // 0..63 loader row
    const int lc = tid & 3;           // 0..3 loader 16B chunk

    // per-kt loader: 4 operand tiles, 128 rows x 32 bf16 each; 2 chunks/thread/tile
    auto load_tiles = [&](int kt, int buf) {
        const uint32_t base = smemU + (uint32_t)buf * (4 * TILEB * 2);
        const bf16* aH = Ahi + (long long)rowBase * lda + kt * 32;
        const bf16* aL = Alo + (long long)rowBase * lda + kt * 32;
        const bf16* bH = Bhi + (long long)colBase * ldb + kt * 32;
        const bf16* bL = Blo + (long long)colBase * ldb + kt * 32;
        #pragma unroll
        for (int half = 0; half < 2; half++) {
            const int r = lr + half * 64;
            const uint32_t d = (uint32_t)(r * (BSTR * 2) + lc * 16);
            const long long s = (long long)r * lda + lc * 8;
            const long long sb = (long long)r * ldb + lc * 8;
            cp_async16(base + d,                  aH + s);
            cp_async16(base + TILEB * 2 + d,      aL + s);
            cp_async16(base + 2 * TILEB * 2 + d,  bH + sb);
            cp_async16(base + 3 * TILEB * 2 + d,  bL + sb);
        }
        cp_commit();
    };

    load_tiles(0, 0);

    for (int kt = 0; kt < KT; kt++) {
        const int buf = kt & 1;
        if (kt + 1 < KT) {
            load_tiles(kt + 1, buf ^ 1);
            cp_wait<1>();
        } else {
            cp_wait<0>();
        }
        __syncthreads();

        const uint32_t* asH = (const uint32_t*)(smem + (size_t)buf * 4 * TILEB);
        const uint32_t* asL = asH + TILEB / 2;
        const uint32_t* bsH = asH + TILEB;          // 2*TILEB/2
        const uint32_t* bsL = asH + 3 * (TILEB / 2);

        #pragma unroll
        for (int ks = 0; ks < 2; ks++) {      // two k16 steps per 32-K stage
            const int kbu = ks * 8 + (lane & 3);          // u32 col
            const int ar  = warpM * 64 + (lane >> 2);
            uint32_t ahi[4][4], alo[4][4];
            #pragma unroll
            for (int mi = 0; mi < 4; mi++) {
                const int r0 = (ar + mi * 16) * 20 + kbu;
                const int r1 = (ar + mi * 16 + 8) * 20 + kbu;
                ahi[mi][0] = asH[r0];     ahi[mi][1] = asH[r1];
                ahi[mi][2] = asH[r0 + 4]; ahi[mi][3] = asH[r1 + 4];
                alo[mi][0] = asL[r0];     alo[mi][1] = asL[r1];
                alo[mi][2] = asL[r0 + 4]; alo[mi][3] = asL[r1 + 4];
            }
            const int br = warpN * 32 + (lane >> 2);
            #pragma unroll
            for (int ni = 0; ni < 4; ni++) {
                const int b0 = (br + ni * 8) * 20 + kbu;
                uint32_t bhi[2], blo[2];
                bhi[0] = bsH[b0]; bhi[1] = bsH[b0 + 4];
                blo[0] = bsL[b0]; blo[1] = bsL[b0 + 4];
                #pragma unroll
                for (int mi = 0; mi < 4; mi++) {
                    mma_bf16(acc[mi][ni], ahi[mi], bhi);
                    mma_bf16(acc[mi][ni], ahi[mi], blo);
                    mma_bf16(acc[mi][ni], alo[mi], bhi);
                }
            }
        }
        __syncthreads();
    }

    // epilogue (m16n8 C fragment layout)
    const int r0 = rowBase + warpM * 64 + (lane >> 2);
    const int c0 = colBase + warpN * 32 + (lane & 3) * 2;
    #pragma unroll
    for (int mi = 0; mi < 4; mi++) {
        #pragma unroll
        for (int ni = 0; ni < 4; ni++) {
            const int row = r0 + mi * 16;
            const int col = c0 + ni * 8;
            float f0 = acc[mi][ni][0] * alpha, f1 = acc[mi][ni][1] * alpha;
            float f2 = acc[mi][ni][2] * alpha, f3 = acc[mi][ni][3] * alpha;
            if (SPLIT_OUT) {
                uint32_t h0, l0, h1, l1;
                split2(f0, f1, h0, l0);
                split2(f2, f3, h1, l1);
                const long long i0 = (offC + (long long)row * ldc + col) >> 1;
                const long long i1 = (offC + (long long)(row + 8) * ldc + col) >> 1;
                ((uint32_t*)Chi)[i0] = h0; ((uint32_t*)Clo)[i0] = l0;
                ((uint32_t*)Chi)[i1] = h1; ((uint32_t*)Clo)[i1] = l1;
            } else {
                float* Cb = C + offC;
                *(float2*)(Cb + (long long)row * ldc + col)       = make_float2(f0, f1);
                *(float2*)(Cb + (long long)(row + 8) * ldc + col) = make_float2(f2, f3);
            }
        }
    }
}

// ---------------------------------------------------------------------------
// Tiled transpose + split: dhi/dlo[c][r] = split(src[r][c]); batched via z
// grid (C/32, R/32, Z), block (32, 8)
// ---------------------------------------------------------------------------
__global__ void __launch_bounds__(256)
transpose_split(const float* __restrict__ src,
                bf16* __restrict__ dhi, bf16* __restrict__ dlo,
                int ldS, int ldD,
                long long sSb, long long sSh, long long sDb, long long sDh,
                int Hdiv)
{
    __shared__ float t[32][33];
    const int z = blockIdx.z, bb = z / Hdiv, hh = z - bb * Hdiv;
    src += bb * sSb + hh * sSh;
    dhi += bb * sDb + hh * sDh;
    dlo += bb * sDb + hh * sDh;
    const int c0 = blockIdx.x * 32, r0 = blockIdx.y * 32;
    const int x = threadIdx.x, y = threadIdx.y;
    #pragma unroll
    for (int j = 0; j < 32; j += 8)
        t[y + j][x] = src[(long long)(r0 + y + j) * ldS + c0 + x];
    __syncthreads();
    #pragma unroll
    for (int j = 0; j < 32; j += 8) {
        float v = t[x][y + j];
        bf16 h = __float2bfloat16_rn(v);
        bf16 l = __float2bfloat16_rn(v - __bfloat162float(h));
        long long idx = (long long)(c0 + y + j) * ldD + r0 + x;
        dhi[idx] = h;
        dlo[idx] = l;
    }
}

// ---------------------------------------------------------------------------
// LayerNorm (+ optional RoPE) with split outputs — one block per row
// ---------------------------------------------------------------------------
template<bool ROPE>
__global__ void __launch_bounds__(256)
ln_split(const float* __restrict__ x,
         const float* __restrict__ gamma, const float* __restrict__ beta,
         bf16* __restrict__ yhi, bf16* __restrict__ ylo,
         bf16* __restrict__ yphi, bf16* __restrict__ yplo)
{
    __shared__ float sy[E_];
    __shared__ float red[256];
    const int r   = blockIdx.x;
    const int s   = r & (S_ - 1);
    const int tid = threadIdx.x;
    const float* xr = x + (long long)r * E_;

    float sum = 0.f;
    #pragma unroll
    for (int i = tid; i < E_; i += 256) { float v = xr[i]; sy[i] = v; sum += v; }
    red[tid] = sum; __syncthreads();
    #pragma unroll
    for (int o = 128; o > 0; o >>= 1) { if (tid < o) red[tid] += red[tid + o]; __syncthreads(); }
    const float mean = red[0] * (1.0f / E_);
    __syncthreads();

    float vs = 0.f;
    #pragma unroll
    for (int i = tid; i < E_; i += 256) { float d = sy[i] - mean; vs += d * d; }
    red[tid] = vs; __syncthreads();
    #pragma unroll
    for (int o = 128; o > 0; o >>= 1) { if (tid < o) red[tid] += red[tid + o]; __syncthreads(); }
    const float rstd = rsqrtf(red[0] * (1.0f / E_) + 1e-6f);
    __syncthreads();

    // normalized values, pairwise; also cache in sy for rope
    #pragma unroll
    for (int j = 0; j < 4; j++) {
        const int i2 = 2 * tid + j * 512;
        float v0 = (sy[i2]     - mean) * rstd * gamma[i2]     + beta[i2];
        float v1 = (sy[i2 + 1] - mean) * rstd * gamma[i2 + 1] + beta[i2 + 1];
        uint32_t h, l;
        split2(v0, v1, h, l);
        const long long o = ((long long)r * E_ + i2) >> 1;
        ((uint32_t*)yhi)[o] = h; ((uint32_t*)ylo)[o] = l;
        red[tid] = 0.f;  // dummy to keep compiler honest (no-op)
        sy[i2] = v0; sy[i2 + 1] = v1;
    }
    if (ROPE) {
        __syncthreads();
        const float l2c = 13.287712379549449f / 1024.0f;  // log2(10000)/half
        #pragma unroll
        for (int j = 0; j < 4; j++) {
            const int i2 = 2 * tid + j * 512;
            const int jj = i2 & 1023;   // freq index (i2<1024 ? i2 : i2-1024)
            float a0 = (float)s * exp2f(-(float)jj * l2c);
            float a1 = (float)s * exp2f(-(float)(jj + 1) * l2c);
            float c0, s0, c1, s1;
            sincosf(a0, &s0, &c0);
            sincosf(a1, &s1, &c1);
            float rot0 = (i2 < 1024)     ? -sy[i2 + 1024]     : sy[i2 - 1024];
            float rot1 = (i2 + 1 < 1024) ? -sy[i2 + 1 + 1024] : sy[i2 + 1 - 1024];
            float v0 = sy[i2] * c0 + rot0 * s0;
            float v1 = sy[i2 + 1] * c1 + rot1 * s1;
            uint32_t h, l;
            split2(v0, v1, h, l);
            const long long o = ((long long)r * E_ + i2) >> 1;
            ((uint32_t*)yphi)[o] = h; ((uint32_t*)yplo)[o] = l;
        }
    }
}

// ---------------------------------------------------------------------------
// Causal softmax with split output. One block per (b,h,s) row.
// ---------------------------------------------------------------------------
__global__ void __launch_bounds__(256)
softmax_split(const float* __restrict__ sc,
              bf16* __restrict__ phi, bf16* __restrict__ plo)
{
    const long long r = blockIdx.x;           // ((b*H+h)*S + s)
    const int s = (int)(r & (S_ - 1));
    const int L = s + 1;
    const float2* row2 = (const float2*)(sc + r * S_);
    const int tid = threadIdx.x;
    __shared__ float red[256];

    float2 v0 = row2[tid];
    float2 v1 = row2[256 + tid];
    const int t0 = 2 * tid, t1 = 512 + 2 * tid;
    float e00 = (t0     < L) ? v0.x : -FLT_MAX;
    float e01 = (t0 + 1 < L) ? v0.y : -FLT_MAX;
    float e10 = (t1     < L) ? v1.x : -FLT_MAX;
    float e11 = (t1 + 1 < L) ? v1.y : -FLT_MAX;

    float mx = fmaxf(fmaxf(e00, e01), fmaxf(e10, e11));
    red[tid] = mx; __syncthreads();
    #pragma unroll
    for (int o = 128; o > 0; o >>= 1) { if (tid < o) red[tid] = fmaxf(red[tid], red[tid + o]); __syncthreads(); }
    mx = red[0]; __syncthreads();

    e00 = (t0     < L) ? expf(e00 - mx) : 0.f;
    e01 = (t0 + 1 < L) ? expf(e01 - mx) : 0.f;
    e10 = (t1     < L) ? expf(e10 - mx) : 0.f;
    e11 = (t1 + 1 < L) ? expf(e11 - mx) : 0.f;

    red[tid] = e00 + e01 + e10 + e11; __syncthreads();
    #pragma unroll
    for (int o = 128; o > 0; o >>= 1) { if (tid < o) red[tid] += red[tid + o]; __syncthreads(); }
    const float inv = 1.0f / red[0];

    uint32_t h0, l0, h1, l1;
    split2(e00 * inv, e01 * inv, h0, l0);
    split2(e10 * inv, e11 * inv, h1, l1);
    const long long o0 = r * 512 + tid;
    const long long o1 = r * 512 + 256 + tid;
    ((uint32_t*)phi)[o0] = h0; ((uint32_t*)plo)[o0] = l0;
    ((uint32_t*)phi)[o1] = h1; ((uint32_t*)plo)[o1] = l1;
}

// ---------------------------------------------------------------------------
// GeGLU elementwise with split output: gg = gelu_exact(G) * U
// ---------------------------------------------------------------------------
__global__ void __launch_bounds__(256)
geglu_split(const float* __restrict__ G, const float* __restrict__ U,
            bf16* __restrict__ gghi, bf16* __restrict__ gglo)
{
    const long long i = ((long long)blockIdx.x * 256 + threadIdx.x) * 4;
    float4 g = *(const float4*)(G + i);
    float4 u = *(const float4*)(U + i);
    const float c = 0.70710678118654752f;
    float r0 = 0.5f * g.x * (1.f + erff(g.x * c)) * u.x;
    float r1 = 0.5f * g.y * (1.f + erff(g.y * c)) * u.y;
    float r2 = 0.5f * g.z * (1.f + erff(g.z * c)) * u.z;
    float r3 = 0.5f * g.w * (1.f + erff(g.w * c)) * u.w;
    uint32_t h0, l0, h1, l1;
    split2(r0, r1, h0, l0);
    split2(r2, r3, h1, l1);
    ((uint32_t*)gghi)[i >> 1]       = h0; ((uint32_t*)gglo)[i >> 1]       = l0;
    ((uint32_t*)gghi)[(i >> 1) + 1] = h1; ((uint32_t*)gglo)[(i >> 1) + 1] = l1;
}

// ---------------------------------------------------------------------------
// Host launch
// ---------------------------------------------------------------------------
extern "C" void kernel_launch(void* const* d_in, const int* in_sizes, int n_in,
                              void* d_out, int out_size)
{
    const float* x      = (const float*)d_in[0];
    const float* gamma1 = (const float*)d_in[1];
    const float* beta1  = (const float*)d_in[2];
    const float* Wq     = (const float*)d_in[3];
    const float* Wk     = (const float*)d_in[4];
    const float* Wv     = (const float*)d_in[5];
    const float* Wo     = (const float*)d_in[6];
    const float* gamma2 = (const float*)d_in[7];
    const float* beta2  = (const float*)d_in[8];
    const float* Wg     = (const float*)d_in[9];
    const float* Wu     = (const float*)d_in[10];
    const float* Wd     = (const float*)d_in[11];
    float* out = (float*)d_out;

    float *v, *sc, *attn, *G, *U;
    cudaGetSymbolAddress((void**)&v,    g_v);
    cudaGetSymbolAddress((void**)&sc,   g_sc);
    cudaGetSymbolAddress((void**)&attn, g_attn);
    cudaGetSymbolAddress((void**)&G,    g_G);
    cudaGetSymbolAddress((void**)&U,    g_U);

    bf16 *y_hi, *y_lo, *yp_hi, *yp_lo, *q_hi, *q_lo, *k_hi, *k_lo;
    bf16 *vT_hi, *vT_lo, *p_hi, *p_lo, *ctx_hi, *ctx_lo, *z_hi, *z_lo, *gg_hi, *gg_lo;
    bf16 *WqT_hi, *WqT_lo, *WkT_hi, *WkT_lo, *WvT_hi, *WvT_lo, *WoT_hi, *WoT_lo;
    bf16 *WgT_hi, *WgT_lo, *WuT_hi, *WuT_lo, *WdT_hi, *WdT_lo;
    cudaGetSymbolAddress((void**)&y_hi,   g_y_hi);   cudaGetSymbolAddress((void**)&y_lo,   g_y_lo);
    cudaGetSymbolAddress((void**)&yp_hi,  g_yp_hi);  cudaGetSymbolAddress((void**)&yp_lo,  g_yp_lo);
    cudaGetSymbolAddress((void**)&q_hi,   g_q_hi);   cudaGetSymbolAddress((void**)&q_lo,   g_q_lo);
    cudaGetSymbolAddress((void**)&k_hi,   g_k_hi);   cudaGetSymbolAddress((void**)&k_lo,   g_k_lo);
    cudaGetSymbolAddress((void**)&vT_hi,  g_vT_hi);  cudaGetSymbolAddress((void**)&vT_lo,  g_vT_lo);
    cudaGetSymbolAddress((void**)&p_hi,   g_p_hi);   cudaGetSymbolAddress((void**)&p_lo,   g_p_lo);
    cudaGetSymbolAddress((void**)&ctx_hi, g_ctx_hi); cudaGetSymbolAddress((void**)&ctx_lo, g_ctx_lo);
    cudaGetSymbolAddress((void**)&z_hi,   g_z_hi);   cudaGetSymbolAddress((void**)&z_lo,   g_z_lo);
    cudaGetSymbolAddress((void**)&gg_hi,  g_gg_hi);  cudaGetSymbolAddress((void**)&gg_lo,  g_gg_lo);
    cudaGetSymbolAddress((void**)&WqT_hi, g_WqT_hi); cudaGetSymbolAddress((void**)&WqT_lo, g_WqT_lo);
    cudaGetSymbolAddress((void**)&WkT_hi, g_WkT_hi); cudaGetSymbolAddress((void**)&WkT_lo, g_WkT_lo);
    cudaGetSymbolAddress((void**)&WvT_hi, g_WvT_hi); cudaGetSymbolAddress((void**)&WvT_lo, g_WvT_lo);
    cudaGetSymbolAddress((void**)&WoT_hi, g_WoT_hi); cudaGetSymbolAddress((void**)&WoT_lo, g_WoT_lo);
    cudaGetSymbolAddress((void**)&WgT_hi, g_WgT_hi); cudaGetSymbolAddress((void**)&WgT_lo, g_WgT_lo);
    cudaGetSymbolAddress((void**)&WuT_hi, g_WuT_hi); cudaGetSymbolAddress((void**)&WuT_lo, g_WuT_lo);
    cudaGetSymbolAddress((void**)&WdT_hi, g_WdT_hi); cudaGetSymbolAddress((void**)&WdT_lo, g_WdT_lo);

    const int SMEM = 2 * 4 * TILEB * 2;   // 81920 bytes
    cudaFuncSetAttribute(mma_gemm<false, false>, cudaFuncAttributeMaxDynamicSharedMemorySize, SMEM);
    cudaFuncSetAttribute(mma_gemm<false, true>,  cudaFuncAttributeMaxDynamicSharedMemorySize, SMEM);
    cudaFuncSetAttribute(mma_gemm<true,  false>, cudaFuncAttributeMaxDynamicSharedMemorySize, SMEM);

    const float qscale = 0.08838834764831845f;   // DH^-0.5
    const dim3 tb(32, 8);

    // 0. weight transposes + split (Bt layout [N][K])
    transpose_split<<<dim3(64, 64, 1),  tb>>>(Wq, WqT_hi, WqT_lo, E_, E_, 0,0, 0,0, 1);
    transpose_split<<<dim3(64, 64, 1),  tb>>>(Wk, WkT_hi, WkT_lo, E_, E_, 0,0, 0,0, 1);
    transpose_split<<<dim3(64, 64, 1),  tb>>>(Wv, WvT_hi, WvT_lo, E_, E_, 0,0, 0,0, 1);
    transpose_split<<<dim3(64, 64, 1),  tb>>>(Wo, WoT_hi, WoT_lo, E_, E_, 0,0, 0,0, 1);
    transpose_split<<<dim3(256, 64, 1), tb>>>(Wg, WgT_hi, WgT_lo, F_, E_, 0,0, 0,0, 1);
    transpose_split<<<dim3(256, 64, 1), tb>>>(Wu, WuT_hi, WuT_lo, F_, E_, 0,0, 0,0, 1);
    transpose_split<<<dim3(64, 256, 1), tb>>>(Wd, WdT_hi, WdT_lo, E_, F_, 0,0, 0,0, 1);

    // 1. LN1 + RoPE (split outputs)
    ln_split<true><<<M_, 256>>>(x, gamma1, beta1, y_hi, y_lo, yp_hi, yp_lo);

    // 2-4. QKV projections: [4096,2048] x [2048,2048]^T
    {
        dim3 g(E_ / 128, M_ / 128, 1);
        mma_gemm<false, true><<<g, 256, SMEM>>>(yp_hi, yp_lo, WqT_hi, WqT_lo,
            nullptr, q_hi, q_lo, E_, E_, E_, E_, 0,0, 0,0, 0,0, 1, qscale);
        mma_gemm<false, true><<<g, 256, SMEM>>>(yp_hi, yp_lo, WkT_hi, WkT_lo,
            nullptr, k_hi, k_lo, E_, E_, E_, E_, 0,0, 0,0, 0,0, 1, 1.0f);
        mma_gemm<false, false><<<g, 256, SMEM>>>(y_hi, y_lo, WvT_hi, WvT_lo,
            v, nullptr, nullptr, E_, E_, E_, E_, 0,0, 0,0, 0,0, 1, 1.0f);
    }

    // 4b. transpose+split v -> vT [B,H,DH,S]
    transpose_split<<<dim3(DH_ / 32, S_ / 32, B_ * H_), tb>>>(
        v, vT_hi, vT_lo, E_, S_,
        (long long)S_ * E_, (long long)DH_,
        (long long)H_ * DH_ * S_, (long long)DH_ * S_, H_);

    // 5. scores = q @ k^T (batched over B*H, causal tile skip) -> fp32
    {
        dim3 g(S_ / 128, S_ / 128, B_ * H_);
        const long long sQb = (long long)S_ * E_, sQh = DH_;
        const long long sSb = (long long)H_ * S_ * S_, sSh = (long long)S_ * S_;
        mma_gemm<true, false><<<g, 256, SMEM>>>(q_hi, q_lo, k_hi, k_lo,
            sc, nullptr, nullptr, DH_, E_, E_, S_,
            sQb, sQh, sQb, sQh, sSb, sSh, H_, 1.0f);
    }

    // 6. causal softmax -> split probs
    softmax_split<<<B_ * H_ * S_, 256>>>(sc, p_hi, p_lo);

    // 7. ctx = probs @ v  -> split ctx
    {
        dim3 g(DH_ / 128, S_ / 128, B_ * H_);
        const long long sSb = (long long)H_ * S_ * S_, sSh = (long long)S_ * S_;
        const long long sVb = (long long)H_ * DH_ * S_, sVh = (long long)DH_ * S_;
        const long long sCb = (long long)S_ * E_, sCh = DH_;
        mma_gemm<false, true><<<g, 256, SMEM>>>(p_hi, p_lo, vT_hi, vT_lo,
            nullptr, ctx_hi, ctx_lo, S_, S_, S_, E_,
            sSb, sSh, sVb, sVh, sCb, sCh, H_, 1.0f);
    }

    // 8. attn = ctx @ Wo -> fp32 (LN2 input)
    {
        dim3 g(E_ / 128, M_ / 128, 1);
        mma_gemm<false, false><<<g, 256, SMEM>>>(ctx_hi, ctx_lo, WoT_hi, WoT_lo,
            attn, nullptr, nullptr, E_, E_, E_, E_, 0,0, 0,0, 0,0, 1, 1.0f);
    }

    // 9. LN2 -> split z
    ln_split<false><<<M_, 256>>>(attn, gamma2, beta2, z_hi, z_lo, nullptr, nullptr);

    // 10-11. gate / up: [4096,2048] x [8192,2048]^T -> fp32 (geglu input)
    {
        dim3 g(F_ / 128, M_ / 128, 1);
        mma_gemm<false, false><<<g, 256, SMEM>>>(z_hi, z_lo, WgT_hi, WgT_lo,
            G, nullptr, nullptr, E_, E_, E_, F_, 0,0, 0,0, 0,0, 1, 1.0f);
        mma_gemm<false, false><<<g, 256, SMEM>>>(z_hi, z_lo, WuT_hi, WuT_lo,
            U, nullptr, nullptr, E_, E_, E_, F_, 0,0, 0,0, 0,0, 1, 1.0f);
    }

    // 12. GeGLU elementwise -> split gg
    {
        long long n = (long long)M_ * F_;
        geglu_split<<<(unsigned)(n / (256 * 4)), 256>>>(G, U, gg_hi, gg_lo);
    }

    // 13. out = gg @ Wd : [4096,8192] x [2048,8192]^T -> fp32 out
    {
        dim3 g(E_ / 128, M_ / 128, 1);
        mma_gemm<false, false><<<g, 256, SMEM>>>(gg_hi, gg_lo, WdT_hi, WdT_lo,
            out, nullptr, nullptr, F_, F_, F_, E_, 0,0, 0,0, 0,0, 1, 1.0f);
    }
}

// round 11
// speedup vs baseline: 2.3486x; 1.0703x over previous
#include <cuda_runtime.h>
#include <cuda_bf16.h>
#include <cstdint>
#include <math.h>
#include <float.h>

// Problem constants
#define B_  4
#define S_  1024
#define E_  2048
#define H_  16
#define DH_ 128
#define F_  8192
#define M_  (B_ * S_)          // 4096 rows

typedef __nv_bfloat16 bf16;

// ---------------------------------------------------------------------------
// Scratch (device globals; allocation-free contract)
// ---------------------------------------------------------------------------
__device__ float g_v   [(size_t)M_ * E_];
__device__ float g_sc  [(size_t)B_ * H_ * S_ * S_]; // raw scores
__device__ float g_attn[(size_t)M_ * E_];
__device__ float g_G   [(size_t)M_ * F_];
__device__ float g_U   [(size_t)M_ * F_];
__device__ bf16 g_y_hi [(size_t)M_ * E_];
__device__ bf16 g_y_lo [(size_t)M_ * E_];
__device__ bf16 g_yp_hi[(size_t)M_ * E_];
__device__ bf16 g_yp_lo[(size_t)M_ * E_];
__device__ bf16 g_q_hi [(size_t)M_ * E_];
__device__ bf16 g_q_lo [(size_t)M_ * E_];
__device__ bf16 g_k_hi [(size_t)M_ * E_];
__device__ bf16 g_k_lo [(size_t)M_ * E_];
__device__ bf16 g_vT_hi[(size_t)M_ * E_];           // [B,H,DH,S]
__device__ bf16 g_vT_lo[(size_t)M_ * E_];
__device__ bf16 g_p_hi [(size_t)B_ * H_ * S_ * S_]; // probs
__device__ bf16 g_p_lo [(size_t)B_ * H_ * S_ * S_];
__device__ bf16 g_ctx_hi[(size_t)M_ * E_];
__device__ bf16 g_ctx_lo[(size_t)M_ * E_];
__device__ bf16 g_z_hi [(size_t)M_ * E_];
__device__ bf16 g_z_lo [(size_t)M_ * E_];
__device__ bf16 g_gg_hi[(size_t)M_ * F_];           // gelu(G)*U
__device__ bf16 g_gg_lo[(size_t)M_ * F_];
__device__ bf16 g_WqT_hi[(size_t)E_ * E_];  __device__ bf16 g_WqT_lo[(size_t)E_ * E_];
__device__ bf16 g_WkT_hi[(size_t)E_ * E_];  __device__ bf16 g_WkT_lo[(size_t)E_ * E_];
__device__ bf16 g_WvT_hi[(size_t)E_ * E_];  __device__ bf16 g_WvT_lo[(size_t)E_ * E_];
__device__ bf16 g_WoT_hi[(size_t)E_ * E_];  __device__ bf16 g_WoT_lo[(size_t)E_ * E_];
__device__ bf16 g_WgT_hi[(size_t)F_ * E_];  __device__ bf16 g_WgT_lo[(size_t)F_ * E_];
__device__ bf16 g_WuT_hi[(size_t)F_ * E_];  __device__ bf16 g_WuT_lo[(size_t)F_ * E_];
__device__ bf16 g_WdT_hi[(size_t)E_ * F_];  __device__ bf16 g_WdT_lo[(size_t)E_ * F_];

// ---------------------------------------------------------------------------
// PTX helpers
// ---------------------------------------------------------------------------
__device__ __forceinline__ uint32_t smem_u32(const void* p) {
    uint32_t a;
    asm("{ .reg .u64 t; cvta.to.shared.u64 t, %1; cvt.u32.u64 %0, t; }"
        : "=r"(a) : "l"(p));
    return a;
}
__device__ __forceinline__ void cp_async16(uint32_t dst, const void* src) {
    asm volatile("cp.async.cg.shared.global [%0], [%1], 16;"
                 :: "r"(dst), "l"(src) : "memory");
}
__device__ __forceinline__ void cp_commit() {
    asm volatile("cp.async.commit_group;" ::: "memory");
}
template<int N> __device__ __forceinline__ void cp_wait() {
    asm volatile("cp.async.wait_group %0;" :: "n"(N) : "memory");
}
__device__ __forceinline__ void ldsm_x4(uint32_t& r0, uint32_t& r1,
                                        uint32_t& r2, uint32_t& r3, uint32_t addr) {
    asm volatile("ldmatrix.sync.aligned.m8n8.x4.shared.b16 {%0,%1,%2,%3}, [%4];"
                 : "=r"(r0), "=r"(r1), "=r"(r2), "=r"(r3) : "r"(addr));
}

// split f32 pair into packed bf16x2 (hi) + packed bf16x2 (lo residual)
__device__ __forceinline__ void split2(float f0, float f1, uint32_t& hi, uint32_t& lo) {
    __nv_bfloat162 h = __floats2bfloat162_rn(f0, f1);
    float h0 = __bfloat162float(__low2bfloat16(h));
    float h1 = __bfloat162float(__high2bfloat16(h));
    __nv_bfloat162 l = __floats2bfloat162_rn(f0 - h0, f1 - h1);
    hi = *reinterpret_cast<uint32_t*>(&h);
    lo = *reinterpret_cast<uint32_t*>(&l);
}

__device__ __forceinline__ void mma_bf16(float* c, const uint32_t* a, const uint32_t* b) {
    asm volatile(
        "mma.sync.aligned.m16n8k16.row.col.f32.bf16.bf16.f32 "
        "{%0,%1,%2,%3}, {%4,%5,%6,%7}, {%8,%9}, {%0,%1,%2,%3};"
        : "+f"(c[0]), "+f"(c[1]), "+f"(c[2]), "+f"(c[3])
        : "r"(a[0]), "r"(a[1]), "r"(a[2]), "r"(a[3]), "r"(b[0]), "r"(b[1]));
}

// ---------------------------------------------------------------------------
// Pre-split bf16 GEMM: C = alpha * (Ahi+Alo)[M,K] * ((Bhi+Blo)[N,K])^T
// 3-term hi*hi + hi*lo + lo*hi, fp32 accumulate. CTA 128x128, K-stage 32,
// cp.async double-buffered, 8 warps (2x4), ldmatrix fragment loads.
// smem row stride 40 bf16 (80B) -> conflict-free ldmatrix phases.
// KLIM: limit K to rowBase+128 (causal probs @ V).
// ---------------------------------------------------------------------------
#define BSTR  40                    // bf16 elems per smem row
#define TILEB (128 * BSTR)          // bf16 elems per tile (5120)
#define TILE_BYTES (TILEB * 2)      // 10240
#define STAGE_BYTES (4 * TILE_BYTES)// 40960

template<bool CAUSAL, bool KLIM, bool SPLIT_OUT>
__global__ void __launch_bounds__(256, 2)
mma_gemm(const bf16* __restrict__ Ahi, const bf16* __restrict__ Alo,
         const bf16* __restrict__ Bhi, const bf16* __restrict__ Blo,
         float* __restrict__ C, bf16* __restrict__ Chi, bf16* __restrict__ Clo,
         int K, int lda, int ldb, int ldc,
         long long sAb, long long sAh,
         long long sBb, long long sBh,
         long long sCb, long long sCh,
         int Hdiv, float alpha)
{
    if (CAUSAL && blockIdx.x > blockIdx.y) return;
    const int rowBase = blockIdx.y * 128;
    const int colBase = blockIdx.x * 128;

    const int z  = blockIdx.z;
    const int bb = z / Hdiv;
    const int hh = z - bb * Hdiv;
    const long long offA = bb * sAb + hh * sAh;
    const long long offB = bb * sBb + hh * sBh;
    const long long offC = bb * sCb + hh * sCh;
    Ahi += offA; Alo += offA;
    Bhi += offB; Blo += offB;

    extern __shared__ bf16 smem[];
    const uint32_t smemU = smem_u32(smem);

    const int tid   = threadIdx.x;
    const int lane  = tid & 31;
    const int wid   = tid >> 5;
    const int warpM = wid >> 2;       // 0..1
    const int warpN = wid & 3;        // 0..3

    // ldmatrix per-lane address components (bytes within a tile)
    // A frag (m16k16): mats {r..r+7,k0-7},{r+8..,k0-7},{r..,k8-15},{r+8..,k8-15}
    const int aRow = warpM * 64 + ((lane >> 3) & 1) * 8 + (lane & 7);
    const uint32_t aCol = (uint32_t)(lane >> 4) * 16;
    uint32_t aAddr[4];
    #pragma unroll
    for (int mi = 0; mi < 4; mi++)
        aAddr[mi] = (uint32_t)(aRow + mi * 16) * (BSTR * 2) + aCol;
    // B frag pair (two n8k16): mats {n..n+7,k0-7},{n..n+7,k8-15},{n+8..,k0-7},{n+8..,k8-15}
    const int bRow = warpN * 32 + (lane >> 4) * 8 + (lane & 7);
    const uint32_t bCol = (uint32_t)((lane >> 3) & 1) * 16;
    uint32_t bAddr[2];
    #pragma unroll
    for (int p = 0; p < 2; p++)
        bAddr[p] = (uint32_t)(bRow + p * 16) * (BSTR * 2) + bCol;

    float acc[4][4][4];
    #pragma unroll
    for (int mi = 0; mi < 4; mi++)
        #pragma unroll
        for (int ni = 0; ni < 4; ni++)
            #pragma unroll
            for (int r = 0; r < 4; r++) acc[mi][ni][r] = 0.f;

    int Keff = K;
    if (KLIM) Keff = min(K, rowBase + 128);
    const int KT = Keff >> 5;

    const int lr = tid >> 2;          // 0..63 loader row
    const int lc = tid & 3;           // 0..3 loader 16B chunk

    auto load_tiles = [&](int kt, int buf) {
        const uint32_t base = smemU + (uint32_t)buf * STAGE_BYTES;
        const bf16* aH = Ahi + (long long)rowBase * lda + kt * 32;
        const bf16* aL = Alo + (long long)rowBase * lda + kt * 32;
        const bf16* bH = Bhi + (long long)colBase * ldb + kt * 32;
        const bf16* bL = Blo + (long long)colBase * ldb + kt * 32;
        #pragma unroll
        for (int half = 0; half < 2; half++) {
            const int r = lr + half * 64;
            const uint32_t d = (uint32_t)(r * (BSTR * 2) + lc * 16);
            const long long s  = (long long)r * lda + lc * 8;
            const long long sb = (long long)r * ldb + lc * 8;
            cp_async16(base + d,                  aH + s);
            cp_async16(base + TILE_BYTES + d,     aL + s);
            cp_async16(base + 2 * TILE_BYTES + d, bH + sb);
            cp_async16(base + 3 * TILE_BYTES + d, bL + sb);
        }
        cp_commit();
    };

    load_tiles(0, 0);

    for (int kt = 0; kt < KT; kt++) {
        const int buf = kt & 1;
        if (kt + 1 < KT) {
            load_tiles(kt + 1, buf ^ 1);
            cp_wait<1>();
        } else {
            cp_wait<0>();
        }
        __syncthreads();

        const uint32_t stage = smemU + (uint32_t)buf * STAGE_BYTES;

        #pragma unroll
        for (int ks = 0; ks < 2; ks++) {      // two k16 steps per 32-K stage
            const uint32_t ko = (uint32_t)ks * 32;   // 16 bf16 = 32 bytes
            uint32_t ahi[4][4], alo[4][4], bhi[2][4], blo[2][4];
            #pragma unroll
            for (int mi = 0; mi < 4; mi++) {
                const uint32_t a = stage + aAddr[mi] + ko;
                ldsm_x4(ahi[mi][0], ahi[mi][1], ahi[mi][2], ahi[mi][3], a);
                ldsm_x4(alo[mi][0], alo[mi][1], alo[mi][2], alo[mi][3], a + TILE_BYTES);
            }
            #pragma unroll
            for (int p = 0; p < 2; p++) {
                const uint32_t b = stage + 2 * TILE_BYTES + bAddr[p] + ko;
                ldsm_x4(bhi[p][0], bhi[p][1], bhi[p][2], bhi[p][3], b);
                ldsm_x4(blo[p][0], blo[p][1], blo[p][2], blo[p][3], b + TILE_BYTES);
            }
            #pragma unroll
            for (int ni = 0; ni < 4; ni++) {
                const uint32_t* bh = &bhi[ni >> 1][(ni & 1) * 2];
                const uint32_t* bl = &blo[ni >> 1][(ni & 1) * 2];
                #pragma unroll
                for (int mi = 0; mi < 4; mi++) {
                    mma_bf16(acc[mi][ni], ahi[mi], bh);
                    mma_bf16(acc[mi][ni], ahi[mi], bl);
                    mma_bf16(acc[mi][ni], alo[mi], bh);
                }
            }
        }
        __syncthreads();
    }

    // epilogue (m16n8 C fragment layout)
    const int r0 = rowBase + warpM * 64 + (lane >> 2);
    const int c0 = colBase + warpN * 32 + (lane & 3) * 2;
    #pragma unroll
    for (int mi = 0; mi < 4; mi++) {
        #pragma unroll
        for (int ni = 0; ni < 4; ni++) {
            const int row = r0 + mi * 16;
            const int col = c0 + ni * 8;
            float f0 = acc[mi][ni][0] * alpha, f1 = acc[mi][ni][1] * alpha;
            float f2 = acc[mi][ni][2] * alpha, f3 = acc[mi][ni][3] * alpha;
            if (SPLIT_OUT) {
                uint32_t h0, l0, h1, l1;
                split2(f0, f1, h0, l0);
                split2(f2, f3, h1, l1);
                const long long i0 = (offC + (long long)row * ldc + col) >> 1;
                const long long i1 = (offC + (long long)(row + 8) * ldc + col) >> 1;
                ((uint32_t*)Chi)[i0] = h0; ((uint32_t*)Clo)[i0] = l0;
                ((uint32_t*)Chi)[i1] = h1; ((uint32_t*)Clo)[i1] = l1;
            } else {
                float* Cb = C + offC;
                *(float2*)(Cb + (long long)row * ldc + col)       = make_float2(f0, f1);
                *(float2*)(Cb + (long long)(row + 8) * ldc + col) = make_float2(f2, f3);
            }
        }
    }
}

// ---------------------------------------------------------------------------
// Tiled transpose + split: dhi/dlo[c][r] = split(src[r][c]); batched via z
// ---------------------------------------------------------------------------
__global__ void __launch_bounds__(256)
transpose_split(const float* __restrict__ src,
                bf16* __restrict__ dhi, bf16* __restrict__ dlo,
                int ldS, int ldD,
                long long sSb, long long sSh, long long sDb, long long sDh,
                int Hdiv)
{
    __shared__ float t[32][33];
    const int z = blockIdx.z, bb = z / Hdiv, hh = z - bb * Hdiv;
    src += bb * sSb + hh * sSh;
    dhi += bb * sDb + hh * sDh;
    dlo += bb * sDb + hh * sDh;
    const int c0 = blockIdx.x * 32, r0 = blockIdx.y * 32;
    const int x = threadIdx.x, y = threadIdx.y;
    #pragma unroll
    for (int j = 0; j < 32; j += 8)
        t[y + j][x] = src[(long long)(r0 + y + j) * ldS + c0 + x];
    __syncthreads();
    #pragma unroll
    for (int j = 0; j < 32; j += 8) {
        float v = t[x][y + j];
        bf16 h = __float2bfloat16_rn(v);
        bf16 l = __float2bfloat16_rn(v - __bfloat162float(h));
        long long idx = (long long)(c0 + y + j) * ldD + r0 + x;
        dhi[idx] = h;
        dlo[idx] = l;
    }
}

// ---------------------------------------------------------------------------
// LayerNorm (+ optional RoPE) with split outputs — one block per row
// ---------------------------------------------------------------------------
template<bool ROPE>
__global__ void __launch_bounds__(256)
ln_split(const float* __restrict__ x,
         const float* __restrict__ gamma, const float* __restrict__ beta,
         bf16* __restrict__ yhi, bf16* __restrict__ ylo,
         bf16* __restrict__ yphi, bf16* __restrict__ yplo)
{
    __shared__ float sy[E_];
    __shared__ float red[256];
    const int r   = blockIdx.x;
    const int s   = r & (S_ - 1);
    const int tid = threadIdx.x;
    const float* xr = x + (long long)r * E_;

    float sum = 0.f;
    #pragma unroll
    for (int i = tid; i < E_; i += 256) { float v = xr[i]; sy[i] = v; sum += v; }
    red[tid] = sum; __syncthreads();
    #pragma unroll
    for (int o = 128; o > 0; o >>= 1) { if (tid < o) red[tid] += red[tid + o]; __syncthreads(); }
    const float mean = red[0] * (1.0f / E_);
    __syncthreads();

    float vs = 0.f;
    #pragma unroll
    for (int i = tid; i < E_; i += 256) { float d = sy[i] - mean; vs += d * d; }
    red[tid] = vs; __syncthreads();
    #pragma unroll
    for (int o = 128; o > 0; o >>= 1) { if (tid < o) red[tid] += red[tid + o]; __syncthreads(); }
    const float rstd = rsqrtf(red[0] * (1.0f / E_) + 1e-6f);
    __syncthreads();

    #pragma unroll
    for (int j = 0; j < 4; j++) {
        const int i2 = 2 * tid + j * 512;
        float v0 = (sy[i2]     - mean) * rstd * gamma[i2]     + beta[i2];
        float v1 = (sy[i2 + 1] - mean) * rstd * gamma[i2 + 1] + beta[i2 + 1];
        uint32_t h, l;
        split2(v0, v1, h, l);
        const long long o = ((long long)r * E_ + i2) >> 1;
        ((uint32_t*)yhi)[o] = h; ((uint32_t*)ylo)[o] = l;
        sy[i2] = v0; sy[i2 + 1] = v1;
    }
    if (ROPE) {
        __syncthreads();
        const float l2c = 13.287712379549449f / 1024.0f;  // log2(10000)/half
        #pragma unroll
        for (int j = 0; j < 4; j++) {
            const int i2 = 2 * tid + j * 512;
            const int jj = i2 & 1023;
            float a0 = (float)s * exp2f(-(float)jj * l2c);
            float a1 = (float)s * exp2f(-(float)(jj + 1) * l2c);
            float c0, s0, c1, s1;
            sincosf(a0, &s0, &c0);
            sincosf(a1, &s1, &c1);
            float rot0 = (i2 < 1024)     ? -sy[i2 + 1024]     : sy[i2 - 1024];
            float rot1 = (i2 + 1 < 1024) ? -sy[i2 + 1 + 1024] : sy[i2 + 1 - 1024];
            float v0 = sy[i2] * c0 + rot0 * s0;
            float v1 = sy[i2 + 1] * c1 + rot1 * s1;
            uint32_t h, l;
            split2(v0, v1, h, l);
            const long long o = ((long long)r * E_ + i2) >> 1;
            ((uint32_t*)yphi)[o] = h; ((uint32_t*)yplo)[o] = l;
        }
    }
}

// ---------------------------------------------------------------------------
// Causal softmax with split output. One block per (b,h,s) row.
// ---------------------------------------------------------------------------
__global__ void __launch_bounds__(256)
softmax_split(const float* __restrict__ sc,
              bf16* __restrict__ phi, bf16* __restrict__ plo)
{
    const long long r = blockIdx.x;
    const int s = (int)(r & (S_ - 1));
    const int L = s + 1;
    const float2* row2 = (const float2*)(sc + r * S_);
    const int tid = threadIdx.x;
    __shared__ float red[256];

    float2 v0 = row2[tid];
    float2 v1 = row2[256 + tid];
    const int t0 = 2 * tid, t1 = 512 + 2 * tid;
    float e00 = (t0     < L) ? v0.x : -FLT_MAX;
    float e01 = (t0 + 1 < L) ? v0.y : -FLT_MAX;
    float e10 = (t1     < L) ? v1.x : -FLT_MAX;
    float e11 = (t1 + 1 < L) ? v1.y : -FLT_MAX;

    float mx = fmaxf(fmaxf(e00, e01), fmaxf(e10, e11));
    red[tid] = mx; __syncthreads();
    #pragma unroll
    for (int o = 128; o > 0; o >>= 1) { if (tid < o) red[tid] = fmaxf(red[tid], red[tid + o]); __syncthreads(); }
    mx = red[0]; __syncthreads();

    e00 = (t0     < L) ? expf(e00 - mx) : 0.f;
    e01 = (t0 + 1 < L) ? expf(e01 - mx) : 0.f;
    e10 = (t1     < L) ? expf(e10 - mx) : 0.f;
    e11 = (t1 + 1 < L) ? expf(e11 - mx) : 0.f;

    red[tid] = e00 + e01 + e10 + e11; __syncthreads();
    #pragma unroll
    for (int o = 128; o > 0; o >>= 1) { if (tid < o) red[tid] += red[tid + o]; __syncthreads(); }
    const float inv = 1.0f / red[0];

    uint32_t h0, l0, h1, l1;
    split2(e00 * inv, e01 * inv, h0, l0);
    split2(e10 * inv, e11 * inv, h1, l1);
    const long long o0 = r * 512 + tid;
    const long long o1 = r * 512 + 256 + tid;
    ((uint32_t*)phi)[o0] = h0; ((uint32_t*)plo)[o0] = l0;
    ((uint32_t*)phi)[o1] = h1; ((uint32_t*)plo)[o1] = l1;
}

// ---------------------------------------------------------------------------
// GeGLU elementwise with split output: gg = gelu_exact(G) * U
// ---------------------------------------------------------------------------
__global__ void __launch_bounds__(256)
geglu_split(const float* __restrict__ G, const float* __restrict__ U,
            bf16* __restrict__ gghi, bf16* __restrict__ gglo)
{
    const long long i = ((long long)blockIdx.x * 256 + threadIdx.x) * 4;
    float4 g = *(const float4*)(G + i);
    float4 u = *(const float4*)(U + i);
    const float c = 0.70710678118654752f;
    float r0 = 0.5f * g.x * (1.f + erff(g.x * c)) * u.x;
    float r1 = 0.5f * g.y * (1.f + erff(g.y * c)) * u.y;
    float r2 = 0.5f * g.z * (1.f + erff(g.z * c)) * u.z;
    float r3 = 0.5f * g.w * (1.f + erff(g.w * c)) * u.w;
    uint32_t h0, l0, h1, l1;
    split2(r0, r1, h0, l0);
    split2(r2, r3, h1, l1);
    ((uint32_t*)gghi)[i >> 1]       = h0; ((uint32_t*)gglo)[i >> 1]       = l0;
    ((uint32_t*)gghi)[(i >> 1) + 1] = h1; ((uint32_t*)gglo)[(i >> 1) + 1] = l1;
}

// ---------------------------------------------------------------------------
// Host launch
// ---------------------------------------------------------------------------
extern "C" void kernel_launch(void* const* d_in, const int* in_sizes, int n_in,
                              void* d_out, int out_size)
{
    const float* x      = (const float*)d_in[0];
    const float* gamma1 = (const float*)d_in[1];
    const float* beta1  = (const float*)d_in[2];
    const float* Wq     = (const float*)d_in[3];
    const float* Wk     = (const float*)d_in[4];
    const float* Wv     = (const float*)d_in[5];
    const float* Wo     = (const float*)d_in[6];
    const float* gamma2 = (const float*)d_in[7];
    const float* beta2  = (const float*)d_in[8];
    const float* Wg     = (const float*)d_in[9];
    const float* Wu     = (const float*)d_in[10];
    const float* Wd     = (const float*)d_in[11];
    float* out = (float*)d_out;

    float *v, *sc, *attn, *G, *U;
    cudaGetSymbolAddress((void**)&v,    g_v);
    cudaGetSymbolAddress((void**)&sc,   g_sc);
    cudaGetSymbolAddress((void**)&attn, g_attn);
    cudaGetSymbolAddress((void**)&G,    g_G);
    cudaGetSymbolAddress((void**)&U,    g_U);

    bf16 *y_hi, *y_lo, *yp_hi, *yp_lo, *q_hi, *q_lo, *k_hi, *k_lo;
    bf16 *vT_hi, *vT_lo, *p_hi, *p_lo, *ctx_hi, *ctx_lo, *z_hi, *z_lo, *gg_hi, *gg_lo;
    bf16 *WqT_hi, *WqT_lo, *WkT_hi, *WkT_lo, *WvT_hi, *WvT_lo, *WoT_hi, *WoT_lo;
    bf16 *WgT_hi, *WgT_lo, *WuT_hi, *WuT_lo, *WdT_hi, *WdT_lo;
    cudaGetSymbolAddress((void**)&y_hi,   g_y_hi);   cudaGetSymbolAddress((void**)&y_lo,   g_y_lo);
    cudaGetSymbolAddress((void**)&yp_hi,  g_yp_hi);  cudaGetSymbolAddress((void**)&yp_lo,  g_yp_lo);
    cudaGetSymbolAddress((void**)&q_hi,   g_q_hi);   cudaGetSymbolAddress((void**)&q_lo,   g_q_lo);
    cudaGetSymbolAddress((void**)&k_hi,   g_k_hi);   cudaGetSymbolAddress((void**)&k_lo,   g_k_lo);
    cudaGetSymbolAddress((void**)&vT_hi,  g_vT_hi);  cudaGetSymbolAddress((void**)&vT_lo,  g_vT_lo);
    cudaGetSymbolAddress((void**)&p_hi,   g_p_hi);   cudaGetSymbolAddress((void**)&p_lo,   g_p_lo);
    cudaGetSymbolAddress((void**)&ctx_hi, g_ctx_hi); cudaGetSymbolAddress((void**)&ctx_lo, g_ctx_lo);
    cudaGetSymbolAddress((void**)&z_hi,   g_z_hi);   cudaGetSymbolAddress((void**)&z_lo,   g_z_lo);
    cudaGetSymbolAddress((void**)&gg_hi,  g_gg_hi);  cudaGetSymbolAddress((void**)&gg_lo,  g_gg_lo);
    cudaGetSymbolAddress((void**)&WqT_hi, g_WqT_hi); cudaGetSymbolAddress((void**)&WqT_lo, g_WqT_lo);
    cudaGetSymbolAddress((void**)&WkT_hi, g_WkT_hi); cudaGetSymbolAddress((void**)&WkT_lo, g_WkT_lo);
    cudaGetSymbolAddress((void**)&WvT_hi, g_WvT_hi); cudaGetSymbolAddress((void**)&WvT_lo, g_WvT_lo);
    cudaGetSymbolAddress((void**)&WoT_hi, g_WoT_hi); cudaGetSymbolAddress((void**)&WoT_lo, g_WoT_lo);
    cudaGetSymbolAddress((void**)&WgT_hi, g_WgT_hi); cudaGetSymbolAddress((void**)&WgT_lo, g_WgT_lo);
    cudaGetSymbolAddress((void**)&WuT_hi, g_WuT_hi); cudaGetSymbolAddress((void**)&WuT_lo, g_WuT_lo);
    cudaGetSymbolAddress((void**)&WdT_hi, g_WdT_hi); cudaGetSymbolAddress((void**)&WdT_lo, g_WdT_lo);

    const int SMEM = 2 * STAGE_BYTES;   // 81920 bytes
    cudaFuncSetAttribute(mma_gemm<false, false, false>, cudaFuncAttributeMaxDynamicSharedMemorySize, SMEM);
    cudaFuncSetAttribute(mma_gemm<false, false, true>,  cudaFuncAttributeMaxDynamicSharedMemorySize, SMEM);
    cudaFuncSetAttribute(mma_gemm<true,  false, false>, cudaFuncAttributeMaxDynamicSharedMemorySize, SMEM);
    cudaFuncSetAttribute(mma_gemm<false, true,  true>,  cudaFuncAttributeMaxDynamicSharedMemorySize, SMEM);

    const float qscale = 0.08838834764831845f;   // DH^-0.5
    const dim3 tb(32, 8);

    // launch 0: LN1 + RoPE (only needs x)
    ln_split<true><<<M_, 256>>>(x, gamma1, beta1, y_hi, y_lo, yp_hi, yp_lo);

    // launches 1-4: attention weight transposes
    transpose_split<<<dim3(64, 64, 1), tb>>>(Wq, WqT_hi, WqT_lo, E_, E_, 0,0, 0,0, 1);
    transpose_split<<<dim3(64, 64, 1), tb>>>(Wk, WkT_hi, WkT_lo, E_, E_, 0,0, 0,0, 1);
    transpose_split<<<dim3(64, 64, 1), tb>>>(Wv, WvT_hi, WvT_lo, E_, E_, 0,0, 0,0, 1);
    transpose_split<<<dim3(64, 64, 1), tb>>>(Wo, WoT_hi, WoT_lo, E_, E_, 0,0, 0,0, 1);

    // launch 5 (ncu -s 5 -c 1 profiles this): Q projection GEMM
    {
        dim3 g(E_ / 128, M_ / 128, 1);
        mma_gemm<false, false, true><<<g, 256, SMEM>>>(yp_hi, yp_lo, WqT_hi, WqT_lo,
            nullptr, q_hi, q_lo, E_, E_, E_, E_, 0,0, 0,0, 0,0, 1, qscale);
        mma_gemm<false, false, true><<<g, 256, SMEM>>>(yp_hi, yp_lo, WkT_hi, WkT_lo,
            nullptr, k_hi, k_lo, E_, E_, E_, E_, 0,0, 0,0, 0,0, 1, 1.0f);
        mma_gemm<false, false, false><<<g, 256, SMEM>>>(y_hi, y_lo, WvT_hi, WvT_lo,
            v, nullptr, nullptr, E_, E_, E_, E_, 0,0, 0,0, 0,0, 1, 1.0f);
    }

    // transpose+split v -> vT [B,H,DH,S]
    transpose_split<<<dim3(DH_ / 32, S_ / 32, B_ * H_), tb>>>(
        v, vT_hi, vT_lo, E_, S_,
        (long long)S_ * E_, (long long)DH_,
        (long long)H_ * DH_ * S_, (long long)DH_ * S_, H_);

    // scores = q @ k^T (batched over B*H, causal tile skip) -> fp32
    {
        dim3 g(S_ / 128, S_ / 128, B_ * H_);
        const long long sQb = (long long)S_ * E_, sQh = DH_;
        const long long sSb = (long long)H_ * S_ * S_, sSh = (long long)S_ * S_;
        mma_gemm<true, false, false><<<g, 256, SMEM>>>(q_hi, q_lo, k_hi, k_lo,
            sc, nullptr, nullptr, DH_, E_, E_, S_,
            sQb, sQh, sQb, sQh, sSb, sSh, H_, 1.0f);
    }

    // causal softmax -> split probs
    softmax_split<<<B_ * H_ * S_, 256>>>(sc, p_hi, p_lo);

    // ctx = probs @ v  (KLIM: skip zero K region) -> split ctx
    {
        dim3 g(DH_ / 128, S_ / 128, B_ * H_);
        const long long sSb = (long long)H_ * S_ * S_, sSh = (long long)S_ * S_;
        const long long sVb = (long long)H_ * DH_ * S_, sVh = (long long)DH_ * S_;
        const long long sCb = (long long)S_ * E_, sCh = DH_;
        mma_gemm<false, true, true><<<g, 256, SMEM>>>(p_hi, p_lo, vT_hi, vT_lo,
            nullptr, ctx_hi, ctx_lo, S_, S_, S_, E_,
            sSb, sSh, sVb, sVh, sCb, sCh, H_, 1.0f);
    }

    // attn = ctx @ Wo -> fp32 (LN2 input)
    {
        dim3 g(E_ / 128, M_ / 128, 1);
        mma_gemm<false, false, false><<<g, 256, SMEM>>>(ctx_hi, ctx_lo, WoT_hi, WoT_lo,
            attn, nullptr, nullptr, E_, E_, E_, E_, 0,0, 0,0, 0,0, 1, 1.0f);
    }

    // LN2 -> split z
    ln_split<false><<<M_, 256>>>(attn, gamma2, beta2, z_hi, z_lo, nullptr, nullptr);

    // FFN weight transposes (deferred; independent until here)
    transpose_split<<<dim3(256, 64, 1), tb>>>(Wg, WgT_hi, WgT_lo, F_, E_, 0,0, 0,0, 1);
    transpose_split<<<dim3(256, 64, 1), tb>>>(Wu, WuT_hi, WuT_lo, F_, E_, 0,0, 0,0, 1);

    // gate / up: [4096,2048] x [8192,2048]^T -> fp32 (geglu input)
    {
        dim3 g(F_ / 128, M_ / 128, 1);
        mma_gemm<false, false, false><<<g, 256, SMEM>>>(z_hi, z_lo, WgT_hi, WgT_lo,
            G, nullptr, nullptr, E_, E_, E_, F_, 0,0, 0,0, 0,0, 1, 1.0f);
        mma_gemm<false, false, false><<<g, 256, SMEM>>>(z_hi, z_lo, WuT_hi, WuT_lo,
            U, nullptr, nullptr, E_, E_, E_, F_, 0,0, 0,0, 0,0, 1, 1.0f);
    }

    // GeGLU elementwise -> split gg
    {
        long long n = (long long)M_ * F_;
        geglu_split<<<(unsigned)(n / (256 * 4)), 256>>>(G, U, gg_hi, gg_lo);
    }

    // Wd transpose, then out = gg @ Wd
    transpose_split<<<dim3(64, 256, 1), tb>>>(Wd, WdT_hi, WdT_lo, E_, F_, 0,0, 0,0, 1);
    {
        dim3 g(E_ / 128, M_ / 128, 1);
        mma_gemm<false, false, false><<<g, 256, SMEM>>>(gg_hi, gg_lo, WdT_hi, WdT_lo,
            out, nullptr, nullptr, F_, F_, F_, E_, 0,0, 0,0, 0,0, 1, 1.0f);
    }
}